// round 1
// baseline (speedup 1.0000x reference)
#include <cuda_runtime.h>
#include <math.h>
#include <float.h>

// Shapes (fixed by the problem)
#define NB  4
#define C   64
#define HH  128
#define HWD (128*128)   // 16384 full-res positions
#define F   4096        // 64x64 pooled positions
#define CQ  8           // query/key channels
#define CV  32          // value channels
#define BF  16          // f-rows per stats block
#define TK  128         // queries per attn block
#define SF  16          // f per stage in attn kernel

// Scratch (device globals; no allocation allowed)
__device__ float g_q[NB*CQ*HWD];   // [b][c][k]
__device__ float g_kp[NB*F*CQ];    // [b][f][c]  (f-major for coalesced stage loads)
__device__ float g_v [NB*F*CV];    // [b][f][c]  raw v, scaled in-place by 1/Z

// ---------------- K1: q = Wq @ x (full res) ----------------
__global__ __launch_bounds__(256) void k_qproj(const float* __restrict__ x,
                                               const float* __restrict__ Wq) {
    __shared__ float wq[CQ*C];
    for (int i = threadIdx.x; i < CQ*C; i += 256) wq[i] = Wq[i];
    __syncthreads();
    int idx = blockIdx.x*256 + threadIdx.x;
    int b = idx >> 14, hw = idx & (HWD-1);
    const float* xp = x + (size_t)b*C*HWD + hw;
    float acc[CQ];
#pragma unroll
    for (int o = 0; o < CQ; o++) acc[o] = 0.f;
#pragma unroll 4
    for (int c = 0; c < C; c++) {
        float xv = xp[(size_t)c*HWD];
#pragma unroll
        for (int o = 0; o < CQ; o++) acc[o] = fmaf(wq[o*C+c], xv, acc[o]);
    }
#pragma unroll
    for (int o = 0; o < CQ; o++) g_q[((b*CQ+o)<<14) + hw] = acc[o];
}

// ---------------- K2: kp = maxpool(Wk@x), v = maxpool(Wv@x) ----------------
__global__ __launch_bounds__(256) void k_kvpool(const float* __restrict__ x,
                                                const float* __restrict__ Wk,
                                                const float* __restrict__ Wv) {
    __shared__ float wk[CQ*C];
    __shared__ float wv[CV*C];
    for (int i = threadIdx.x; i < CQ*C; i += 256) wk[i] = Wk[i];
    for (int i = threadIdx.x; i < CV*C; i += 256) wv[i] = Wv[i];
    __syncthreads();
    int idx = blockIdx.x*256 + threadIdx.x;
    int b = idx >> 12, f = idx & (F-1);
    int ph = f >> 6, pw = f & 63;
    int hw0 = (ph*2)*HH + pw*2;
    const float* xb = x + (size_t)b*C*HWD;

    // K branch (8 outputs)
    {
        float kmax[CQ];
#pragma unroll
        for (int o = 0; o < CQ; o++) kmax[o] = -FLT_MAX;
#pragma unroll
        for (int p = 0; p < 4; p++) {
            int hw = hw0 + (p>>1)*HH + (p&1);
            float a[CQ];
#pragma unroll
            for (int o = 0; o < CQ; o++) a[o] = 0.f;
            for (int c = 0; c < C; c++) {
                float xv = xb[(size_t)c*HWD + hw];
#pragma unroll
                for (int o = 0; o < CQ; o++) a[o] = fmaf(wk[o*C+c], xv, a[o]);
            }
#pragma unroll
            for (int o = 0; o < CQ; o++) kmax[o] = fmaxf(kmax[o], a[o]);
        }
#pragma unroll
        for (int o = 0; o < CQ; o++) g_kp[(b*F+f)*CQ + o] = kmax[o];
    }
    // V branch (32 outputs)
    {
        float vmax[CV];
#pragma unroll
        for (int o = 0; o < CV; o++) vmax[o] = -FLT_MAX;
#pragma unroll
        for (int p = 0; p < 4; p++) {
            int hw = hw0 + (p>>1)*HH + (p&1);
            float a[CV];
#pragma unroll
            for (int o = 0; o < CV; o++) a[o] = 0.f;
            for (int c = 0; c < C; c++) {
                float xv = xb[(size_t)c*HWD + hw];
#pragma unroll
                for (int o = 0; o < CV; o++) a[o] = fmaf(wv[o*C+c], xv, a[o]);
            }
#pragma unroll
            for (int o = 0; o < CV; o++) vmax[o] = fmaxf(vmax[o], a[o]);
        }
#pragma unroll
        for (int o = 0; o < CV; o++) g_v[(b*F+f)*CV + o] = vmax[o];
    }
}

// ---------------- K3: Z[f] = sum_k exp(s[f,k]); scale v by 1/Z in place ----------------
// No max-subtraction: |s| is bounded ~35 by the input distributions; fp32 exp
// is safe far beyond that, and softmax is shift-invariant so results match.
__global__ __launch_bounds__(256) void k_stats() {
    int b  = blockIdx.x >> 8;            // F/BF = 256 chunks per batch
    int f0 = (blockIdx.x & 255) * BF;
    __shared__ float kp_s[BF][CQ];
    if (threadIdx.x < BF*CQ)
        kp_s[threadIdx.x>>3][threadIdx.x&7] = g_kp[(b*F+f0)*CQ + threadIdx.x];
    __syncthreads();
    float z[BF];
#pragma unroll
    for (int f = 0; f < BF; f++) z[f] = 0.f;

    for (int kk = threadIdx.x; kk < HWD; kk += 256) {
        float qv[CQ];
#pragma unroll
        for (int c = 0; c < CQ; c++) qv[c] = g_q[((b*CQ+c)<<14) + kk];
#pragma unroll
        for (int f = 0; f < BF; f++) {
            float s = 0.f;
#pragma unroll
            for (int c = 0; c < CQ; c++) s = fmaf(kp_s[f][c], qv[c], s);
            z[f] += __expf(s);
        }
    }
    // warp reduce
    int lane = threadIdx.x & 31, wid = threadIdx.x >> 5;
#pragma unroll
    for (int f = 0; f < BF; f++) {
#pragma unroll
        for (int off = 16; off > 0; off >>= 1)
            z[f] += __shfl_xor_sync(0xffffffffu, z[f], off);
    }
    __shared__ float rz[BF][8];
    if (lane == 0) {
#pragma unroll
        for (int f = 0; f < BF; f++) rz[f][wid] = z[f];
    }
    __syncthreads();
    __shared__ float finv[BF];
    if (threadIdx.x < BF) {
        int f = threadIdx.x;
        float Z = 0.f;
#pragma unroll
        for (int w = 0; w < 8; w++) Z += rz[f][w];
        finv[f] = 1.f / Z;
    }
    __syncthreads();
    for (int i = threadIdx.x; i < BF*CV; i += 256) {
        int f = i >> 5;
        g_v[(b*F+f0)*CV + i] *= finv[f];
    }
}

// ---------------- K4: out = Wo @ (vn . exp(Kp^T Q)) * gamma + x ----------------
// Per block: one batch, TK=128 queries, full 32-channel output tile.
// Staged over f in chunks of SF=16: E-tile (exp scores) in smem, then a
// register-microtiled (4c x 4k) FMA GEMM against vn.
__global__ __launch_bounds__(256) void k_attn(const float* __restrict__ x,
                                              const float* __restrict__ Wo,
                                              const float* __restrict__ gamma,
                                              float* __restrict__ out) {
    __shared__ float wo_s[C*CV];                       // 8KB
    __shared__ __align__(16) float kp_s[SF][CQ];
    __shared__ __align__(16) float vn_s[SF][CV];       // 2KB
    __shared__ __align__(16) float e_s[SF][TK];        // 8KB
    __shared__ __align__(16) float out_s[CV][TK];      // 16KB

    int tid = threadIdx.x;
    int b = blockIdx.y;
    int kbase = blockIdx.x * TK;
    for (int i = tid; i < C*CV; i += 256) wo_s[i] = Wo[i];

    int klane = tid & (TK-1);
    float qv[CQ];
#pragma unroll
    for (int c = 0; c < CQ; c++) qv[c] = g_q[((b*CQ+c)<<14) + kbase + klane];

    float acc[4][4];
#pragma unroll
    for (int i = 0; i < 4; i++)
#pragma unroll
        for (int j = 0; j < 4; j++) acc[i][j] = 0.f;

    int c0 = ((tid>>5) & 7) * 4;   // 0..28
    int k0 = (tid & 31) * 4;       // 0..124
    int fh = (tid>>7) * 8;         // 0 or 8

    for (int fs = 0; fs < F; fs += SF) {
        __syncthreads();   // previous accumulate done reading e_s/vn_s
        for (int i = tid; i < SF*CV; i += 256)
            vn_s[i>>5][i&31] = g_v[(b*F+fs)*CV + i];       // contiguous
        if (tid < SF*CQ)
            kp_s[tid>>3][tid&7] = g_kp[(b*F+fs)*CQ + tid]; // contiguous
        __syncthreads();   // stage data visible

        // E tile: each thread computes 8 exp-scores for its query column
#pragma unroll
        for (int j = 0; j < 8; j++) {
            int f = fh + j;
            float s = 0.f;
#pragma unroll
            for (int c = 0; c < CQ; c++) s = fmaf(kp_s[f][c], qv[c], s);
            e_s[f][klane] = __expf(s);
        }
        __syncthreads();   // E visible

        // GEMM micro-tile: acc[c0..c0+3][k0..k0+3] += vn[:,f] x E[f,:]
#pragma unroll
        for (int f = 0; f < SF; f++) {
            float4 e4 = *reinterpret_cast<const float4*>(&e_s[f][k0]);
            float4 a4 = *reinterpret_cast<const float4*>(&vn_s[f][c0]);
            acc[0][0] = fmaf(a4.x, e4.x, acc[0][0]);
            acc[0][1] = fmaf(a4.x, e4.y, acc[0][1]);
            acc[0][2] = fmaf(a4.x, e4.z, acc[0][2]);
            acc[0][3] = fmaf(a4.x, e4.w, acc[0][3]);
            acc[1][0] = fmaf(a4.y, e4.x, acc[1][0]);
            acc[1][1] = fmaf(a4.y, e4.y, acc[1][1]);
            acc[1][2] = fmaf(a4.y, e4.z, acc[1][2]);
            acc[1][3] = fmaf(a4.y, e4.w, acc[1][3]);
            acc[2][0] = fmaf(a4.z, e4.x, acc[2][0]);
            acc[2][1] = fmaf(a4.z, e4.y, acc[2][1]);
            acc[2][2] = fmaf(a4.z, e4.z, acc[2][2]);
            acc[2][3] = fmaf(a4.z, e4.w, acc[2][3]);
            acc[3][0] = fmaf(a4.w, e4.x, acc[3][0]);
            acc[3][1] = fmaf(a4.w, e4.y, acc[3][1]);
            acc[3][2] = fmaf(a4.w, e4.z, acc[3][2]);
            acc[3][3] = fmaf(a4.w, e4.w, acc[3][3]);
        }
    }

    __syncthreads();
#pragma unroll
    for (int i = 0; i < 4; i++)
#pragma unroll
        for (int j = 0; j < 4; j++)
            out_s[c0+i][k0+j] = acc[i][j];
    __syncthreads();

    // Epilogue: y = Wo @ out32, result = gamma*y + x
    float col[CV];
#pragma unroll
    for (int c = 0; c < CV; c++) col[c] = out_s[c][klane];
    float g = *gamma;
    int co0 = (tid>>7) * 32;   // threads 0-127: co 0..31, 128-255: co 32..63
#pragma unroll 4
    for (int co = 0; co < 32; co++) {
        float y = 0.f;
#pragma unroll
        for (int c = 0; c < CV; c++) y = fmaf(wo_s[(co0+co)*CV + c], col[c], y);
        size_t oidx = ((size_t)(b*C + co0 + co) << 14) + kbase + klane;
        out[oidx] = fmaf(g, y, x[oidx]);
    }
}

extern "C" void kernel_launch(void* const* d_in, const int* in_sizes, int n_in,
                              void* d_out, int out_size) {
    const float* x     = (const float*)d_in[0];
    const float* Wq    = (const float*)d_in[1];
    const float* Wk    = (const float*)d_in[2];
    const float* Wv    = (const float*)d_in[3];
    const float* Wo    = (const float*)d_in[4];
    const float* gamma = (const float*)d_in[5];
    float* out = (float*)d_out;

    k_qproj <<< NB*HWD/256, 256 >>> (x, Wq);
    k_kvpool<<< NB*F/256,   256 >>> (x, Wk, Wv);
    k_stats <<< NB*(F/BF),  256 >>> ();
    dim3 g4(HWD/TK, NB);
    k_attn  <<< g4, 256 >>> (x, Wo, gamma, out);
}

// round 3
// speedup vs baseline: 1.5746x; 1.5746x over previous
#include <cuda_runtime.h>
#include <cuda_bf16.h>
#include <math.h>
#include <float.h>
#include <stdint.h>

// Shapes (fixed by the problem)
#define NB  4
#define C   64
#define HH  128
#define HWD (128*128)   // 16384 full-res positions
#define F   4096        // 64x64 pooled positions
#define CQ  8           // query/key channels
#define CV  32          // value channels
#define BF  16          // f-rows per stats block
#define TK  128         // queries per attn block (MMA M)
#define SFC 64          // f per stage
#define VSTR 80         // vn smem row stride in bytes (pad 64 -> 80 for ldmatrix bank spread)

// ---------------- scratch (device globals) ----------------
__device__ float g_q[NB*CQ*HWD];           // [b][c][k]
__device__ float g_kp[NB*F*CQ];            // [b][f][c]
__device__ float g_v [NB*F*CV];            // [b][f][c] raw pooled v
__device__ __nv_bfloat16 g_vt[NB*F*CV];    // [b][f][c] v/Z in bf16 (B operand)

// ---------------- PTX helpers (all baseline-PTX, no arch-specific features) ----
__device__ __forceinline__ uint32_t smem_u32(const void* p) {
    uint32_t a;
    asm("{ .reg .u64 t; cvta.to.shared.u64 t, %1; cvt.u32.u64 %0, t; }" : "=r"(a) : "l"(p));
    return a;
}
#define STS128(a, r0, r1, r2, r3) \
    asm volatile("st.shared.v4.b32 [%0], {%1, %2, %3, %4};" \
        :: "r"((uint32_t)(a)), "r"(r0), "r"(r1), "r"(r2), "r"(r3) : "memory")
// result = {lo=a, hi=b}
#define CVT_BF16X2_F32(res, a, b) \
    asm("cvt.rn.bf16x2.f32 %0, %1, %2;" : "=r"(res) : "f"(b), "f"(a))

__device__ __forceinline__ void ldmatrix_x4_trans(uint32_t& r0, uint32_t& r1,
                                                  uint32_t& r2, uint32_t& r3,
                                                  uint32_t addr) {
    asm volatile("ldmatrix.sync.aligned.m8n8.x4.trans.shared.b16 {%0,%1,%2,%3}, [%4];"
        : "=r"(r0), "=r"(r1), "=r"(r2), "=r"(r3) : "r"(addr));
}
__device__ __forceinline__ void mma16816(float* d, const uint32_t* a,
                                         uint32_t b0, uint32_t b1) {
    asm volatile(
      "mma.sync.aligned.m16n8k16.row.col.f32.bf16.bf16.f32 "
      "{%0,%1,%2,%3}, {%4,%5,%6,%7}, {%8,%9}, {%0,%1,%2,%3};"
      : "+f"(d[0]), "+f"(d[1]), "+f"(d[2]), "+f"(d[3])
      : "r"(a[0]), "r"(a[1]), "r"(a[2]), "r"(a[3]), "r"(b0), "r"(b1));
}

// ---------------- K1: q = Wq @ x ----------------
__global__ __launch_bounds__(256) void k_qproj(const float* __restrict__ x,
                                               const float* __restrict__ Wq) {
    __shared__ float wq[CQ*C];
    for (int i = threadIdx.x; i < CQ*C; i += 256) wq[i] = Wq[i];
    __syncthreads();
    int idx = blockIdx.x*256 + threadIdx.x;
    int b = idx >> 14, hw = idx & (HWD-1);
    const float* xp = x + (size_t)b*C*HWD + hw;
    float acc[CQ];
#pragma unroll
    for (int o = 0; o < CQ; o++) acc[o] = 0.f;
#pragma unroll 4
    for (int c = 0; c < C; c++) {
        float xv = xp[(size_t)c*HWD];
#pragma unroll
        for (int o = 0; o < CQ; o++) acc[o] = fmaf(wq[o*C+c], xv, acc[o]);
    }
#pragma unroll
    for (int o = 0; o < CQ; o++) g_q[((b*CQ+o)<<14) + hw] = acc[o];
}

// ---------------- K2: kp = maxpool(Wk@x), v = maxpool(Wv@x) ----------------
__global__ __launch_bounds__(256) void k_kvpool(const float* __restrict__ x,
                                                const float* __restrict__ Wk,
                                                const float* __restrict__ Wv) {
    __shared__ float wk[CQ*C];
    __shared__ float wv[CV*C];
    for (int i = threadIdx.x; i < CQ*C; i += 256) wk[i] = Wk[i];
    for (int i = threadIdx.x; i < CV*C; i += 256) wv[i] = Wv[i];
    __syncthreads();
    int idx = blockIdx.x*256 + threadIdx.x;
    int b = idx >> 12, f = idx & (F-1);
    int ph = f >> 6, pw = f & 63;
    int hw0 = (ph*2)*HH + pw*2;
    const float* xb = x + (size_t)b*C*HWD;
    {
        float kmax[CQ];
#pragma unroll
        for (int o = 0; o < CQ; o++) kmax[o] = -FLT_MAX;
#pragma unroll
        for (int p = 0; p < 4; p++) {
            int hw = hw0 + (p>>1)*HH + (p&1);
            float a[CQ];
#pragma unroll
            for (int o = 0; o < CQ; o++) a[o] = 0.f;
            for (int c = 0; c < C; c++) {
                float xv = xb[(size_t)c*HWD + hw];
#pragma unroll
                for (int o = 0; o < CQ; o++) a[o] = fmaf(wk[o*C+c], xv, a[o]);
            }
#pragma unroll
            for (int o = 0; o < CQ; o++) kmax[o] = fmaxf(kmax[o], a[o]);
        }
#pragma unroll
        for (int o = 0; o < CQ; o++) g_kp[(b*F+f)*CQ + o] = kmax[o];
    }
    {
        float vmax[CV];
#pragma unroll
        for (int o = 0; o < CV; o++) vmax[o] = -FLT_MAX;
#pragma unroll
        for (int p = 0; p < 4; p++) {
            int hw = hw0 + (p>>1)*HH + (p&1);
            float a[CV];
#pragma unroll
            for (int o = 0; o < CV; o++) a[o] = 0.f;
            for (int c = 0; c < C; c++) {
                float xv = xb[(size_t)c*HWD + hw];
#pragma unroll
                for (int o = 0; o < CV; o++) a[o] = fmaf(wv[o*C+c], xv, a[o]);
            }
#pragma unroll
            for (int o = 0; o < CV; o++) vmax[o] = fmaxf(vmax[o], a[o]);
        }
#pragma unroll
        for (int o = 0; o < CV; o++) g_v[(b*F+f)*CV + o] = vmax[o];
    }
}

// ---------------- K3: Z[f]; write g_vt[b][f][c] = bf16(v/Z) ----------------
__global__ __launch_bounds__(256) void k_stats() {
    int b  = blockIdx.x >> 8;
    int f0 = (blockIdx.x & 255) * BF;
    __shared__ float kp_s[BF][CQ];
    if (threadIdx.x < BF*CQ)
        kp_s[threadIdx.x>>3][threadIdx.x&7] = g_kp[(b*F+f0)*CQ + threadIdx.x];
    __syncthreads();
    float z[BF];
#pragma unroll
    for (int f = 0; f < BF; f++) z[f] = 0.f;

    for (int kk = threadIdx.x; kk < HWD; kk += 256) {
        float qv[CQ];
#pragma unroll
        for (int c = 0; c < CQ; c++) qv[c] = g_q[((b*CQ+c)<<14) + kk];
#pragma unroll
        for (int f = 0; f < BF; f++) {
            float s = 0.f;
#pragma unroll
            for (int c = 0; c < CQ; c++) s = fmaf(kp_s[f][c], qv[c], s);
            z[f] += __expf(s);
        }
    }
    int lane = threadIdx.x & 31, wid = threadIdx.x >> 5;
#pragma unroll
    for (int f = 0; f < BF; f++) {
#pragma unroll
        for (int off = 16; off > 0; off >>= 1)
            z[f] += __shfl_xor_sync(0xffffffffu, z[f], off);
    }
    __shared__ float rz[BF][8];
    if (lane == 0) {
#pragma unroll
        for (int f = 0; f < BF; f++) rz[f][wid] = z[f];
    }
    __syncthreads();
    __shared__ float finv[BF];
    if (threadIdx.x < BF) {
        int f = threadIdx.x;
        float Z = 0.f;
#pragma unroll
        for (int w = 0; w < 8; w++) Z += rz[f][w];
        finv[f] = 1.f / Z;
    }
    __syncthreads();
    for (int i = threadIdx.x; i < BF*CV; i += 256) {
        int f = i >> 5, c = i & 31;
        float val = g_v[(b*F + f0 + f)*CV + c] * finv[f];
        g_vt[((b*F + f0 + f) << 5) + c] = __float2bfloat16(val);
    }
}

// ---------------- K4: mma.sync attention GEMM + Wo epilogue ----------------
// Per block: queries [kbase,kbase+128), 32 channels, one batch.
// D[128,32] fp32 regs = sum over f of E[128q,f](bf16) x vn[f,32c](bf16).
// A fragments (exp scores) are computed directly in registers; B via ldmatrix.
__global__ __launch_bounds__(256) void k_attn_mma(const float* __restrict__ x,
                                                  const float* __restrict__ Wo,
                                                  const float* __restrict__ gamma,
                                                  float* __restrict__ out) {
    __shared__ float kp_s[SFC*CQ];                    // 2KB
    __shared__ __align__(16) char vn_s[SFC*VSTR];     // 5120B
    __shared__ float wo_s[C*CV];                      // 8KB
    __shared__ float out_s[TK][33];                   // 16.9KB

    const int tid = threadIdx.x;
    const int w = tid >> 5, lane = tid & 31;
    const int g = lane >> 2, tg = lane & 3;
    const int b = blockIdx.y;
    const int kbase = blockIdx.x * TK;

    for (int i = tid; i < C*CV; i += 256) wo_s[i] = Wo[i];

    // two query rows per thread (m16n8k16 A-frag rows g and g+8 of warp tile)
    const int la = w*16 + g;          // local rows
    const int qa = kbase + la, qb = qa + 8;
    float qva[CQ], qvb[CQ];
#pragma unroll
    for (int c = 0; c < CQ; c++) {
        qva[c] = g_q[((b*CQ+c)<<14) + qa];
        qvb[c] = g_q[((b*CQ+c)<<14) + qb];
    }

    float acc[4][4];
#pragma unroll
    for (int i = 0; i < 4; i++)
#pragma unroll
        for (int j = 0; j < 4; j++) acc[i][j] = 0.f;

    const uint32_t vbase = smem_u32(vn_s);
    // ldmatrix.x4.trans lane addressing: lanes 0-15 rows k0..k0+15 (col seg 0),
    // lanes 16-31 same rows at +16B (cols 8..15)
    const uint32_t ldbase = vbase + (lane & 15)*VSTR + ((lane >> 4) & 1)*16;

    const float4* kp4 = reinterpret_cast<const float4*>(kp_s);

    for (int st = 0; st < F/SFC; st++) {
        const int fs = st * SFC;
        __syncthreads();   // previous stage's ldmatrix reads done
        // stage vn tile [64f][32c] bf16, rows padded to VSTR bytes
        {
            int f = tid >> 2, seg = tid & 3;
            const uint4 vv = *reinterpret_cast<const uint4*>(
                g_vt + ((b*F + fs + f) << 5) + seg*8);
            STS128(vbase + f*VSTR + seg*16, vv.x, vv.y, vv.z, vv.w);
        }
        kp_s[tid]       = g_kp[(b*F+fs)*CQ + tid];
        kp_s[tid + 256] = g_kp[(b*F+fs)*CQ + tid + 256];
        __syncthreads();

#pragma unroll
        for (int kc = 0; kc < 4; kc++) {
            // ---- A fragment: scores -> exp -> bf16x2, straight in registers
            const int f0 = kc*16 + tg*2;
            float ea[4], eb[4];   // j: 0:f0, 1:f0+1, 2:f0+8, 3:f0+9
#pragma unroll
            for (int j = 0; j < 4; j++) {
                const int fr = f0 + (j >> 1)*8 + (j & 1);
                const float4 k0 = kp4[2*fr], k1 = kp4[2*fr + 1];
                float sa = k0.x*qva[0], sb = k0.x*qvb[0];
                sa = fmaf(k0.y, qva[1], sa); sb = fmaf(k0.y, qvb[1], sb);
                sa = fmaf(k0.z, qva[2], sa); sb = fmaf(k0.z, qvb[2], sb);
                sa = fmaf(k0.w, qva[3], sa); sb = fmaf(k0.w, qvb[3], sb);
                sa = fmaf(k1.x, qva[4], sa); sb = fmaf(k1.x, qvb[4], sb);
                sa = fmaf(k1.y, qva[5], sa); sb = fmaf(k1.y, qvb[5], sb);
                sa = fmaf(k1.z, qva[6], sa); sb = fmaf(k1.z, qvb[6], sb);
                sa = fmaf(k1.w, qva[7], sa); sb = fmaf(k1.w, qvb[7], sb);
                ea[j] = __expf(sa); eb[j] = __expf(sb);
            }
            uint32_t A[4];
            CVT_BF16X2_F32(A[0], ea[0], ea[1]);   // row g,    k lo-half
            CVT_BF16X2_F32(A[1], eb[0], eb[1]);   // row g+8,  k lo-half
            CVT_BF16X2_F32(A[2], ea[2], ea[3]);   // row g,    k hi-half
            CVT_BF16X2_F32(A[3], eb[2], eb[3]);   // row g+8,  k hi-half

            // ---- B fragments via ldmatrix.trans (vn rows = k/f, cols = channels)
            const uint32_t la0 = ldbase + kc*16*VSTR;
            uint32_t b0, b1, b2, b3, b4, b5, b6, b7;
            ldmatrix_x4_trans(b0, b1, b2, b3, la0);        // channels 0..15
            ldmatrix_x4_trans(b4, b5, b6, b7, la0 + 32);   // channels 16..31

            mma16816(acc[0], A, b0, b1);
            mma16816(acc[1], A, b2, b3);
            mma16816(acc[2], A, b4, b5);
            mma16816(acc[3], A, b6, b7);
        }
    }

    // ---- epilogue: acc -> smem, then y = Wo @ out32, out = gamma*y + x
    __syncthreads();
#pragma unroll
    for (int nc = 0; nc < 4; nc++) {
        out_s[la    ][nc*8 + tg*2    ] = acc[nc][0];
        out_s[la    ][nc*8 + tg*2 + 1] = acc[nc][1];
        out_s[la + 8][nc*8 + tg*2    ] = acc[nc][2];
        out_s[la + 8][nc*8 + tg*2 + 1] = acc[nc][3];
    }
    __syncthreads();

    const int klane = tid & 127;
    float col[CV];
#pragma unroll
    for (int c = 0; c < CV; c++) col[c] = out_s[klane][c];
    const float gm = *gamma;
    const int co0 = (tid >> 7) * 32;
#pragma unroll 4
    for (int co = 0; co < 32; co++) {
        float y = 0.f;
#pragma unroll
        for (int c = 0; c < CV; c++) y = fmaf(wo_s[(co0+co)*CV + c], col[c], y);
        size_t oidx = ((size_t)(b*C + co0 + co) << 14) + kbase + klane;
        out[oidx] = fmaf(gm, y, x[oidx]);
    }
}

extern "C" void kernel_launch(void* const* d_in, const int* in_sizes, int n_in,
                              void* d_out, int out_size) {
    const float* x     = (const float*)d_in[0];
    const float* Wq    = (const float*)d_in[1];
    const float* Wk    = (const float*)d_in[2];
    const float* Wv    = (const float*)d_in[3];
    const float* Wo    = (const float*)d_in[4];
    const float* gamma = (const float*)d_in[5];
    float* out = (float*)d_out;

    k_qproj <<< NB*HWD/256, 256 >>> (x, Wq);
    k_kvpool<<< NB*F/256,   256 >>> (x, Wk, Wv);
    k_stats <<< NB*(F/BF),  256 >>> ();
    dim3 g4(HWD/TK, NB);
    k_attn_mma <<< g4, 256 >>> (x, Wo, gamma, out);
}

// round 4
// speedup vs baseline: 2.8291x; 1.7967x over previous
#include <cuda_runtime.h>
#include <cuda_bf16.h>
#include <math.h>
#include <float.h>
#include <stdint.h>

// Shapes (fixed by the problem)
#define NB  4
#define C   64
#define HH  128
#define HWD (128*128)   // 16384 full-res positions
#define F   4096        // 64x64 pooled positions
#define CQ  8           // query/key channels
#define CV  32          // value channels
#define TK  128         // queries per attn block (MMA M)
#define SFC 64          // f per stage in attn
#define VSTR 80         // vn smem row stride bytes (64 -> 80 pad, conflict-free ldmatrix)
#define LOG2E 1.4426950408889634f

// ---------------- scratch (device globals) ----------------
__device__ float g_q  [NB*CQ*HWD];         // [b][c][k]  tf32-rounded q
__device__ float g_kpt[NB*CQ*F];           // [b][c][f]  tf32-rounded kp * log2e
__device__ float g_v  [NB*F*CV];           // [b][f][c]  raw pooled v
__device__ __nv_bfloat16 g_vt[NB*F*CV];    // [b][f][c]  v/Z bf16 (V-MMA B operand)

// ---------------- PTX helpers (baseline PTX only) ----------------
__device__ __forceinline__ uint32_t smem_u32(const void* p) {
    uint32_t a;
    asm("{ .reg .u64 t; cvta.to.shared.u64 t, %1; cvt.u32.u64 %0, t; }" : "=r"(a) : "l"(p));
    return a;
}
#define STS128(a, r0, r1, r2, r3) \
    asm volatile("st.shared.v4.b32 [%0], {%1, %2, %3, %4};" \
        :: "r"((uint32_t)(a)), "r"(r0), "r"(r1), "r"(r2), "r"(r3) : "memory")
// res = bf16x2 {lo=a, hi=b}
#define CVT_BF16X2_F32(res, a, b) \
    asm("cvt.rn.bf16x2.f32 %0, %1, %2;" : "=r"(res) : "f"(b), "f"(a))
#define EX2F(d, s) asm("ex2.approx.f32 %0, %1;" : "=f"(d) : "f"(s))
#define TF32R(u, v) asm("cvt.rna.tf32.f32 %0, %1;" : "=r"(u) : "f"(v))

__device__ __forceinline__ void ldmatrix_x4_trans(uint32_t& r0, uint32_t& r1,
                                                  uint32_t& r2, uint32_t& r3,
                                                  uint32_t addr) {
    asm volatile("ldmatrix.sync.aligned.m8n8.x4.trans.shared.b16 {%0,%1,%2,%3}, [%4];"
        : "=r"(r0), "=r"(r1), "=r"(r2), "=r"(r3) : "r"(addr));
}
// bf16 m16n8k16, accumulate
__device__ __forceinline__ void mma16816(float* d, const uint32_t* a,
                                         uint32_t b0, uint32_t b1) {
    asm volatile(
      "mma.sync.aligned.m16n8k16.row.col.f32.bf16.bf16.f32 "
      "{%0,%1,%2,%3}, {%4,%5,%6,%7}, {%8,%9}, {%0,%1,%2,%3};"
      : "+f"(d[0]), "+f"(d[1]), "+f"(d[2]), "+f"(d[3])
      : "r"(a[0]), "r"(a[1]), "r"(a[2]), "r"(a[3]), "r"(b0), "r"(b1));
}
// tf32 m16n8k8, C = 0 (fresh scores)
__device__ __forceinline__ void mma_tf32_z(float& d0, float& d1, float& d2, float& d3,
                                           uint32_t a0, uint32_t a1, uint32_t a2, uint32_t a3,
                                           uint32_t b0, uint32_t b1) {
    asm volatile(
      "mma.sync.aligned.m16n8k8.row.col.f32.tf32.tf32.f32 "
      "{%0,%1,%2,%3}, {%4,%5,%6,%7}, {%8,%9}, {%10,%11,%12,%13};"
      : "=f"(d0), "=f"(d1), "=f"(d2), "=f"(d3)
      : "r"(a0), "r"(a1), "r"(a2), "r"(a3), "r"(b0), "r"(b1),
        "f"(0.f), "f"(0.f), "f"(0.f), "f"(0.f));
}

// ---------------- K1: q = tf32(Wq @ x) ----------------
__global__ __launch_bounds__(256) void k_qproj(const float* __restrict__ x,
                                               const float* __restrict__ Wq) {
    __shared__ float wq[CQ*C];
    for (int i = threadIdx.x; i < CQ*C; i += 256) wq[i] = Wq[i];
    __syncthreads();
    int idx = blockIdx.x*256 + threadIdx.x;
    int b = idx >> 14, hw = idx & (HWD-1);
    const float* xp = x + (size_t)b*C*HWD + hw;
    float acc[CQ];
#pragma unroll
    for (int o = 0; o < CQ; o++) acc[o] = 0.f;
#pragma unroll 4
    for (int c = 0; c < C; c++) {
        float xv = xp[(size_t)c*HWD];
#pragma unroll
        for (int o = 0; o < CQ; o++) acc[o] = fmaf(wq[o*C+c], xv, acc[o]);
    }
#pragma unroll
    for (int o = 0; o < CQ; o++) {
        uint32_t u; TF32R(u, acc[o]);
        g_q[((b*CQ+o)<<14) + hw] = __uint_as_float(u);
    }
}

// ---------------- K2: kp_t = tf32(maxpool(Wk@x)*log2e), v = maxpool(Wv@x) -------
__global__ __launch_bounds__(256) void k_kvpool(const float* __restrict__ x,
                                                const float* __restrict__ Wk,
                                                const float* __restrict__ Wv) {
    __shared__ float wk[CQ*C];
    __shared__ float wv[CV*C];
    for (int i = threadIdx.x; i < CQ*C; i += 256) wk[i] = Wk[i];
    for (int i = threadIdx.x; i < CV*C; i += 256) wv[i] = Wv[i];
    __syncthreads();
    int idx = blockIdx.x*256 + threadIdx.x;
    int b = idx >> 12, f = idx & (F-1);
    int ph = f >> 6, pw = f & 63;
    int hw0 = (ph*2)*HH + pw*2;
    const float* xb = x + (size_t)b*C*HWD;
    {
        float kmax[CQ];
#pragma unroll
        for (int o = 0; o < CQ; o++) kmax[o] = -FLT_MAX;
#pragma unroll
        for (int p = 0; p < 4; p++) {
            int hw = hw0 + (p>>1)*HH + (p&1);
            float a[CQ];
#pragma unroll
            for (int o = 0; o < CQ; o++) a[o] = 0.f;
            for (int c = 0; c < C; c++) {
                float xv = xb[(size_t)c*HWD + hw];
#pragma unroll
                for (int o = 0; o < CQ; o++) a[o] = fmaf(wk[o*C+c], xv, a[o]);
            }
#pragma unroll
            for (int o = 0; o < CQ; o++) kmax[o] = fmaxf(kmax[o], a[o]);
        }
#pragma unroll
        for (int o = 0; o < CQ; o++) {
            uint32_t u; TF32R(u, kmax[o] * LOG2E);
            g_kpt[((b*CQ+o)<<12) + f] = __uint_as_float(u);
        }
    }
    {
        float vmax[CV];
#pragma unroll
        for (int o = 0; o < CV; o++) vmax[o] = -FLT_MAX;
#pragma unroll
        for (int p = 0; p < 4; p++) {
            int hw = hw0 + (p>>1)*HH + (p&1);
            float a[CV];
#pragma unroll
            for (int o = 0; o < CV; o++) a[o] = 0.f;
            for (int c = 0; c < C; c++) {
                float xv = xb[(size_t)c*HWD + hw];
#pragma unroll
                for (int o = 0; o < CV; o++) a[o] = fmaf(wv[o*C+c], xv, a[o]);
            }
#pragma unroll
            for (int o = 0; o < CV; o++) vmax[o] = fmaxf(vmax[o], a[o]);
        }
#pragma unroll
        for (int o = 0; o < CV; o++) g_v[(b*F+f)*CV + o] = vmax[o];
    }
}

// ---------------- K3: MMA-based Z + write g_vt = bf16(v/Z) ----------------
// Block = one batch, 64 f. Warps: wf = w&3 -> 16-f m-tile; wq = w>>2 -> q half.
// S^T[f,q] via tf32 MMA (A = kp persistent), ex2, Z-rowsum via bf16 ones-MMA
// accumulated in registers across all q.
__global__ __launch_bounds__(256) void k_stats_mma() {
    const int blk = blockIdx.x;
    const int b = blk >> 6;
    const int f0blk = (blk & 63) * 64;
    const int tid = threadIdx.x;
    const int w = tid >> 5, lane = tid & 31;
    const int g = lane >> 2, tg = lane & 3;
    const int wf = w & 3, wq = w >> 2;
    const int fm = f0blk + wf*16;

    // persistent A (kp) tf32 fragments: rows f=g,g+8; cols c=tg,tg+4
    const float* kpt = g_kpt + ((size_t)(b*CQ) << 12);
    const uint32_t a0 = __float_as_uint(kpt[(tg    <<12) + fm + g    ]);
    const uint32_t a1 = __float_as_uint(kpt[(tg    <<12) + fm + g + 8]);
    const uint32_t a2 = __float_as_uint(kpt[((tg+4)<<12) + fm + g    ]);
    const uint32_t a3 = __float_as_uint(kpt[((tg+4)<<12) + fm + g + 8]);

    const float* qp = g_q + ((size_t)(b*CQ) << 14);
    const int q0 = wq * (HWD/2);
    const uint32_t ONES = 0x3F803F80u;   // bf16x2 (1.0, 1.0)

    float z[4] = {0.f, 0.f, 0.f, 0.f};

    for (int st = 0; st < (HWD/2)/SFC; st++) {   // 128 stages of 64 q
        const int qs = q0 + st*SFC;
#pragma unroll
        for (int tp = 0; tp < 4; tp++) {         // pairs of 8-q tiles
            uint32_t A4[4];
#pragma unroll
            for (int h = 0; h < 2; h++) {
                const int qc = qs + (2*tp + h)*8 + g;
                const uint32_t b0 = __float_as_uint(__ldg(qp + (tg    <<14) + qc));
                const uint32_t b1 = __float_as_uint(__ldg(qp + ((tg+4)<<14) + qc));
                float s0, s1, s2, s3;
                mma_tf32_z(s0, s1, s2, s3, a0, a1, a2, a3, b0, b1);
                float e0, e1, e2, e3;
                EX2F(e0, s0); EX2F(e1, s1); EX2F(e2, s2); EX2F(e3, s3);
                CVT_BF16X2_F32(A4[2*h],     e0, e1);   // row g   (f), q-pair
                CVT_BF16X2_F32(A4[2*h + 1], e2, e3);   // row g+8 (f), q-pair
            }
            mma16816(z, A4, ONES, ONES);   // Z partial: c0 -> f=g, c2 -> f=g+8
        }
    }

    __shared__ float zs[2][64];
    if (tg == 0) {
        zs[wq][wf*16 + g    ] = z[0];
        zs[wq][wf*16 + g + 8] = z[2];
    }
    __syncthreads();
    __shared__ float zinv[64];
    if (tid < 64) zinv[tid] = 1.f / (zs[0][tid] + zs[1][tid]);
    __syncthreads();

    for (int i = tid; i < 64*CV; i += 256) {
        int f = i >> 5, c = i & 31;
        float val = g_v[((size_t)(b*F + f0blk + f))*CV + c] * zinv[f];
        g_vt[(((size_t)(b*F + f0blk + f)) << 5) + c] = __float2bfloat16(val);
    }
}

// ---------------- K4: fully tensorized attention + Wo epilogue ----------------
// Scores: tf32 MMA (A = q persistent, B = kp via LDG) -> ex2 -> bf16 A-frags
// (score accumulator layout == V-MMA A-frag layout) -> bf16 V-MMA vs vn.
__global__ __launch_bounds__(256) void k_attn_mma(const float* __restrict__ x,
                                                  const float* __restrict__ Wo,
                                                  const float* __restrict__ gamma,
                                                  float* __restrict__ out) {
    __shared__ __align__(16) char vn_s[SFC*VSTR];     // 5KB
    __shared__ float wo_s[C*CV];                      // 8KB
    __shared__ float out_s[TK][33];                   // 16.9KB

    const int tid = threadIdx.x;
    const int w = tid >> 5, lane = tid & 31;
    const int g = lane >> 2, tg = lane & 3;
    const int b = blockIdx.y;
    const int kbase = blockIdx.x * TK;

    for (int i = tid; i < C*CV; i += 256) wo_s[i] = Wo[i];

    // persistent A (q) tf32 fragments: rows qa=kbase+w*16+g, qb=+8; cols tg,tg+4
    const int la = w*16 + g;
    const int qa = kbase + la, qb = qa + 8;
    const float* qp = g_q + ((size_t)(b*CQ) << 14);
    const uint32_t aq0 = __float_as_uint(qp[(tg    <<14) + qa]);
    const uint32_t aq1 = __float_as_uint(qp[(tg    <<14) + qb]);
    const uint32_t aq2 = __float_as_uint(qp[((tg+4)<<14) + qa]);
    const uint32_t aq3 = __float_as_uint(qp[((tg+4)<<14) + qb]);

    const float* kpt = g_kpt + ((size_t)(b*CQ) << 12);

    float acc[4][4];
#pragma unroll
    for (int i = 0; i < 4; i++)
#pragma unroll
        for (int j = 0; j < 4; j++) acc[i][j] = 0.f;

    const uint32_t vbase = smem_u32(vn_s);
    const uint32_t ldbase = vbase + (lane & 15)*VSTR + ((lane >> 4) & 1)*16;

    for (int st = 0; st < F/SFC; st++) {
        const int fs = st * SFC;
        __syncthreads();   // previous stage's ldmatrix reads done
        {
            int f = tid >> 2, seg = tid & 3;
            const uint4 vv = *reinterpret_cast<const uint4*>(
                g_vt + (((size_t)(b*F + fs + f)) << 5) + seg*8);
            STS128(vbase + f*VSTR + seg*16, vv.x, vv.y, vv.z, vv.w);
        }
        __syncthreads();

#pragma unroll
        for (int tp = 0; tp < 4; tp++) {     // 16 f per iteration
            uint32_t A4[4];
#pragma unroll
            for (int h = 0; h < 2; h++) {
                const int f0 = fs + (2*tp + h)*8;
                const uint32_t kb0 = __float_as_uint(__ldg(kpt + (tg    <<12) + f0 + g));
                const uint32_t kb1 = __float_as_uint(__ldg(kpt + ((tg+4)<<12) + f0 + g));
                float s0, s1, s2, s3;
                mma_tf32_z(s0, s1, s2, s3, aq0, aq1, aq2, aq3, kb0, kb1);
                float e0, e1, e2, e3;
                EX2F(e0, s0); EX2F(e1, s1); EX2F(e2, s2); EX2F(e3, s3);
                CVT_BF16X2_F32(A4[2*h],     e0, e1);   // row qa, f-pair
                CVT_BF16X2_F32(A4[2*h + 1], e2, e3);   // row qb, f-pair
            }
            // V-MMA over this 16-f chunk
            const uint32_t la0 = ldbase + tp*16*VSTR;
            uint32_t b0, b1, b2, b3, b4, b5, b6, b7;
            ldmatrix_x4_trans(b0, b1, b2, b3, la0);        // channels 0..15
            ldmatrix_x4_trans(b4, b5, b6, b7, la0 + 32);   // channels 16..31
            mma16816(acc[0], A4, b0, b1);
            mma16816(acc[1], A4, b2, b3);
            mma16816(acc[2], A4, b4, b5);
            mma16816(acc[3], A4, b6, b7);
        }
    }

    // ---- epilogue: acc -> smem, y = Wo @ out32, out = gamma*y + x
    __syncthreads();
#pragma unroll
    for (int nc = 0; nc < 4; nc++) {
        out_s[la    ][nc*8 + tg*2    ] = acc[nc][0];
        out_s[la    ][nc*8 + tg*2 + 1] = acc[nc][1];
        out_s[la + 8][nc*8 + tg*2    ] = acc[nc][2];
        out_s[la + 8][nc*8 + tg*2 + 1] = acc[nc][3];
    }
    __syncthreads();

    const int klane = tid & 127;
    float col[CV];
#pragma unroll
    for (int c = 0; c < CV; c++) col[c] = out_s[klane][c];
    const float gm = *gamma;
    const int co0 = (tid >> 7) * 32;
#pragma unroll 4
    for (int co = 0; co < 32; co++) {
        float y = 0.f;
#pragma unroll
        for (int c = 0; c < CV; c++) y = fmaf(wo_s[(co0+co)*CV + c], col[c], y);
        size_t oidx = ((size_t)(b*C + co0 + co) << 14) + kbase + klane;
        out[oidx] = fmaf(gm, y, x[oidx]);
    }
}

extern "C" void kernel_launch(void* const* d_in, const int* in_sizes, int n_in,
                              void* d_out, int out_size) {
    const float* x     = (const float*)d_in[0];
    const float* Wq    = (const float*)d_in[1];
    const float* Wk    = (const float*)d_in[2];
    const float* Wv    = (const float*)d_in[3];
    const float* Wo    = (const float*)d_in[4];
    const float* gamma = (const float*)d_in[5];
    float* out = (float*)d_out;

    k_qproj   <<< NB*HWD/256, 256 >>> (x, Wq);
    k_kvpool  <<< NB*F/256,   256 >>> (x, Wk, Wv);
    k_stats_mma <<< NB*64, 256 >>> ();
    dim3 g4(HWD/TK, NB);
    k_attn_mma <<< g4, 256 >>> (x, Wo, gamma, out);
}

// round 5
// speedup vs baseline: 3.2482x; 1.1481x over previous
#include <cuda_runtime.h>
#include <cuda_bf16.h>
#include <math.h>
#include <float.h>
#include <stdint.h>

// Shapes (fixed by the problem)
#define NB  4
#define C   64
#define HH  128
#define HWD (128*128)   // 16384 full-res positions per batch
#define F   4096        // 64x64 pooled positions per batch
#define CQ  8           // query/key channels
#define CV  32          // value channels
#define TK  128         // queries per attn block (MMA M)
#define SFC 128         // f per stage in attn
#define USTR 144        // u smem row stride bytes (128 -> 144 pad, conflict-free ldmatrix)
#define LOG2E 1.4426950408889634f

// ---------------- scratch (device globals) ----------------
__device__ float g_q  [NB*CQ*HWD];         // [b][c][k]  tf32-rounded q
__device__ float g_kpt[NB*CQ*F];           // [b][c][f]  tf32-rounded kp * log2e
__device__ float g_v  [NB*F*CV];           // [b][f][c]  raw pooled v
__device__ float g_z  [NB*F];              // Z[b][f] (atomic accum)
__device__ __nv_bfloat16 g_u[NB*F*C];      // [b][f][o]  bf16( Wo @ (v/Z) )  (V-MMA B operand)

// ---------------- PTX helpers (baseline PTX only) ----------------
__device__ __forceinline__ uint32_t smem_u32(const void* p) {
    uint32_t a;
    asm("{ .reg .u64 t; cvta.to.shared.u64 t, %1; cvt.u32.u64 %0, t; }" : "=r"(a) : "l"(p));
    return a;
}
// res = bf16x2 {lo=a, hi=b}
#define CVT_BF16X2_F32(res, a, b) \
    asm("cvt.rn.bf16x2.f32 %0, %1, %2;" : "=r"(res) : "f"(b), "f"(a))
#define EX2F(d, s) asm("ex2.approx.f32 %0, %1;" : "=f"(d) : "f"(s))
#define TF32R(u, v) asm("cvt.rna.tf32.f32 %0, %1;" : "=r"(u) : "f"(v))
#define CP_ASYNC16(dst, src) \
    asm volatile("cp.async.ca.shared.global [%0], [%1], 16;" :: "r"(dst), "l"(src))
#define CP_COMMIT asm volatile("cp.async.commit_group;" ::: "memory")
#define CP_WAIT0  asm volatile("cp.async.wait_group 0;" ::: "memory")

__device__ __forceinline__ void ldmatrix_x4_trans(uint32_t& r0, uint32_t& r1,
                                                  uint32_t& r2, uint32_t& r3,
                                                  uint32_t addr) {
    asm volatile("ldmatrix.sync.aligned.m8n8.x4.trans.shared.b16 {%0,%1,%2,%3}, [%4];"
        : "=r"(r0), "=r"(r1), "=r"(r2), "=r"(r3) : "r"(addr));
}
// bf16 m16n8k16, accumulate
__device__ __forceinline__ void mma16816(float* d, const uint32_t* a,
                                         uint32_t b0, uint32_t b1) {
    asm volatile(
      "mma.sync.aligned.m16n8k16.row.col.f32.bf16.bf16.f32 "
      "{%0,%1,%2,%3}, {%4,%5,%6,%7}, {%8,%9}, {%0,%1,%2,%3};"
      : "+f"(d[0]), "+f"(d[1]), "+f"(d[2]), "+f"(d[3])
      : "r"(a[0]), "r"(a[1]), "r"(a[2]), "r"(a[3]), "r"(b0), "r"(b1));
}
// tf32 m16n8k8, C = 0 (fresh scores)
__device__ __forceinline__ void mma_tf32_z(float& d0, float& d1, float& d2, float& d3,
                                           uint32_t a0, uint32_t a1, uint32_t a2, uint32_t a3,
                                           uint32_t b0, uint32_t b1) {
    asm volatile(
      "mma.sync.aligned.m16n8k8.row.col.f32.tf32.tf32.f32 "
      "{%0,%1,%2,%3}, {%4,%5,%6,%7}, {%8,%9}, {%10,%11,%12,%13};"
      : "=f"(d0), "=f"(d1), "=f"(d2), "=f"(d3)
      : "r"(a0), "r"(a1), "r"(a2), "r"(a3), "r"(b0), "r"(b1),
        "f"(0.f), "f"(0.f), "f"(0.f), "f"(0.f));
}

// ---------------- K1: merged projections + 2x2 maxpool via shfl ----------------
// One thread per full-res position; 2x2 cell = 4 adjacent lanes (bits 0,1 of tid).
__global__ __launch_bounds__(128) void k_proj(const float* __restrict__ x,
                                              const float* __restrict__ Wq,
                                              const float* __restrict__ Wk,
                                              const float* __restrict__ Wv) {
    __shared__ float wT[C][48];   // [c][0:8 q | 8:16 k | 16:48 v]
    for (int i = threadIdx.x; i < C*48; i += 128) {
        int c = i / 48, j = i - c*48;
        float v;
        if (j < 8)       v = Wq[j*C + c];
        else if (j < 16) v = Wk[(j-8)*C + c];
        else             v = Wv[(j-16)*C + c];
        wT[c][j] = v;
    }
    __syncthreads();

    const int t = threadIdx.x;
    const int p = blockIdx.x*128 + t;
    const int cell = p >> 2;                 // global 2x2 cell
    const int b = cell >> 12;
    const int f = cell & 4095;               // pooled index within batch
    const int ph = f >> 6, pw = f & 63;
    const int h = 2*ph + ((t >> 1) & 1);
    const int w = 2*pw + (t & 1);
    const int hw = h*HH + w;
    const float* xp = x + (size_t)b*C*HWD + hw;

    float acc[48];
#pragma unroll
    for (int j = 0; j < 48; j++) acc[j] = 0.f;

#pragma unroll 4
    for (int c = 0; c < C; c++) {
        const float xv = __ldg(xp + c*HWD);
        const float4* wr = reinterpret_cast<const float4*>(&wT[c][0]);
#pragma unroll
        for (int j4 = 0; j4 < 12; j4++) {
            float4 ww = wr[j4];
            acc[4*j4+0] = fmaf(ww.x, xv, acc[4*j4+0]);
            acc[4*j4+1] = fmaf(ww.y, xv, acc[4*j4+1]);
            acc[4*j4+2] = fmaf(ww.z, xv, acc[4*j4+2]);
            acc[4*j4+3] = fmaf(ww.w, xv, acc[4*j4+3]);
        }
    }

    // q outputs (full res), tf32-rounded
#pragma unroll
    for (int o = 0; o < CQ; o++) {
        uint32_t u; TF32R(u, acc[o]);
        g_q[((b*CQ+o)<<14) + hw] = __uint_as_float(u);
    }

    // 2x2 max-pool for k and v via shuffles (lane bits 0,1 = w,h parity)
#pragma unroll
    for (int j = 8; j < 48; j++) {
        float m = acc[j];
        m = fmaxf(m, __shfl_xor_sync(0xffffffffu, m, 1));
        m = fmaxf(m, __shfl_xor_sync(0xffffffffu, m, 2));
        acc[j] = m;
    }
    if ((t & 3) == 0) {
#pragma unroll
        for (int o = 0; o < CQ; o++) {
            uint32_t u; TF32R(u, acc[8+o] * LOG2E);
            g_kpt[((b*CQ+o)<<12) + f] = __uint_as_float(u);
        }
        float* vp = g_v + ((size_t)(b*F + f))*CV;
#pragma unroll
        for (int o = 0; o < CV; o++) vp[o] = acc[16+o];
        g_z[b*F + f] = 0.f;
    }
}

// ---------------- K2: partial Z via score-MMA + ones-MMA, atomic accumulate ----
// Block: one batch, 64 f, 1/8 of q. Warps: wf = w&3 -> 16-f tile; wq = w>>2 -> q half.
__global__ __launch_bounds__(256) void k_stats_mma() {
    const int blk = blockIdx.x;
    const int b = blk >> 9;                   // 64 fblk * 8 qsplit = 512 per batch
    const int r = blk & 511;
    const int f0blk = (r >> 3) * 64;
    const int qsp = r & 7;
    const int tid = threadIdx.x;
    const int w = tid >> 5, lane = tid & 31;
    const int g = lane >> 2, tg = lane & 3;
    const int wf = w & 3, wq = w >> 2;
    const int fm = f0blk + wf*16;

    // persistent A (kp) tf32 fragments: rows f=g,g+8; cols c=tg,tg+4
    const float* kpt = g_kpt + ((size_t)(b*CQ) << 12);
    const uint32_t a0 = __float_as_uint(kpt[(tg    <<12) + fm + g    ]);
    const uint32_t a1 = __float_as_uint(kpt[(tg    <<12) + fm + g + 8]);
    const uint32_t a2 = __float_as_uint(kpt[((tg+4)<<12) + fm + g    ]);
    const uint32_t a3 = __float_as_uint(kpt[((tg+4)<<12) + fm + g + 8]);

    const float* qp = g_q + ((size_t)(b*CQ) << 14);
    const int q0 = qsp*2048 + wq*1024;
    const uint32_t ONES = 0x3F803F80u;   // bf16x2 (1.0, 1.0)

    float z[4] = {0.f, 0.f, 0.f, 0.f};

    for (int st = 0; st < 16; st++) {        // 16 stages of 64 q
        const int qs = q0 + st*64;
#pragma unroll
        for (int tp = 0; tp < 4; tp++) {
            uint32_t A4[4];
#pragma unroll
            for (int h = 0; h < 2; h++) {
                const int qc = qs + (2*tp + h)*8 + g;
                const uint32_t b0 = __float_as_uint(__ldg(qp + (tg    <<14) + qc));
                const uint32_t b1 = __float_as_uint(__ldg(qp + ((tg+4)<<14) + qc));
                float s0, s1, s2, s3;
                mma_tf32_z(s0, s1, s2, s3, a0, a1, a2, a3, b0, b1);
                float e0, e1, e2, e3;
                EX2F(e0, s0); EX2F(e1, s1); EX2F(e2, s2); EX2F(e3, s3);
                CVT_BF16X2_F32(A4[2*h],     e0, e1);
                CVT_BF16X2_F32(A4[2*h + 1], e2, e3);
            }
            mma16816(z, A4, ONES, ONES);   // z0 -> f=g, z2 -> f=g+8
        }
    }

    __shared__ float zs[2][64];
    if (tg == 0) {
        zs[wq][wf*16 + g    ] = z[0];
        zs[wq][wf*16 + g + 8] = z[2];
    }
    __syncthreads();
    if (tid < 64)
        atomicAdd(&g_z[b*F + f0blk + tid], zs[0][tid] + zs[1][tid]);
}

// ---------------- K3: u[f][o] = bf16( (Wo @ v[f]) / Z[f] ) ----------------
__global__ __launch_bounds__(256) void k_uvt(const float* __restrict__ Wo) {
    __shared__ float wo_s[C*CV];   // 8KB
    const int tid = threadIdx.x;
    for (int i = tid; i < C*CV; i += 256) wo_s[i] = Wo[i];
    __syncthreads();

    const int fi = blockIdx.x*128 + (tid >> 1);     // over NB*F
    const int og = (tid & 1) * 32;
    const float zi = 1.f / g_z[fi];

    float vv[CV];
    const float4* vp = reinterpret_cast<const float4*>(g_v + (size_t)fi*CV);
#pragma unroll
    for (int i = 0; i < 8; i++) {
        float4 t4 = vp[i];
        vv[4*i] = t4.x; vv[4*i+1] = t4.y; vv[4*i+2] = t4.z; vv[4*i+3] = t4.w;
    }

    uint32_t packed[16];
#pragma unroll
    for (int oo = 0; oo < 32; oo += 2) {
        float y0 = 0.f, y1 = 0.f;
        const float* w0 = wo_s + (og + oo)*CV;
#pragma unroll
        for (int c = 0; c < CV; c++) {
            y0 = fmaf(w0[c],      vv[c], y0);
            y1 = fmaf(w0[CV + c], vv[c], y1);
        }
        CVT_BF16X2_F32(packed[oo >> 1], y0*zi, y1*zi);
    }
    uint4* up = reinterpret_cast<uint4*>(
        reinterpret_cast<char*>(g_u) + ((size_t)fi*C + og)*2);
    const uint4* ps = reinterpret_cast<const uint4*>(packed);
#pragma unroll
    for (int i = 0; i < 4; i++) up[i] = ps[i];
}

// ---------------- K4: tensorized attention, u-folded, cp.async pipelined ------
// out[o,q] = gamma * sum_f u[o,f] * E[f,q] + x[o,q]
__global__ __launch_bounds__(256) void k_attn_mma(const float* __restrict__ x,
                                                  const float* __restrict__ gamma,
                                                  float* __restrict__ out) {
    __shared__ __align__(16) char us[2][SFC*USTR];   // 2 x 18432B

    const int tid = threadIdx.x;
    const int w = tid >> 5, lane = tid & 31;
    const int g = lane >> 2, tg = lane & 3;
    const int b = blockIdx.y;
    const int kbase = blockIdx.x * TK;

    // persistent A (q) tf32 fragments: rows qa, qb; cols tg, tg+4
    const int la = w*16 + g;
    const int qa = kbase + la, qb = qa + 8;
    const float* qp = g_q + ((size_t)(b*CQ) << 14);
    const uint32_t aq0 = __float_as_uint(qp[(tg    <<14) + qa]);
    const uint32_t aq1 = __float_as_uint(qp[(tg    <<14) + qb]);
    const uint32_t aq2 = __float_as_uint(qp[((tg+4)<<14) + qa]);
    const uint32_t aq3 = __float_as_uint(qp[((tg+4)<<14) + qb]);

    const float* kpt = g_kpt + ((size_t)(b*CQ) << 12);
    const char* ubat = reinterpret_cast<const char*>(g_u) + (((size_t)b*F) << 7);

    float acc[8][4];
#pragma unroll
    for (int i = 0; i < 8; i++)
#pragma unroll
        for (int j = 0; j < 4; j++) acc[i][j] = 0.f;

    const uint32_t ub = smem_u32(us);

    // prologue: stage 0 copy (4 x 16B per thread; row = 128B of u)
#pragma unroll
    for (int k = 0; k < 4; k++) {
        int id = tid + k*256, row = id >> 3, seg = id & 7;
        CP_ASYNC16(ub + row*USTR + seg*16, ubat + ((size_t)row << 7) + seg*16);
    }
    CP_COMMIT;

    const int NST = F / SFC;   // 32
    for (int st = 0; st < NST; st++) {
        CP_WAIT0;
        __syncthreads();
        if (st + 1 < NST) {
            const uint32_t dst = ub + ((st+1) & 1)*18432;
            const char* src = ubat + (((size_t)(st+1)*SFC) << 7);
#pragma unroll
            for (int k = 0; k < 4; k++) {
                int id = tid + k*256, row = id >> 3, seg = id & 7;
                CP_ASYNC16(dst + row*USTR + seg*16, src + ((size_t)row << 7) + seg*16);
            }
            CP_COMMIT;
        }
        const int fs = st * SFC;
        const uint32_t ldb = ub + (st & 1)*18432 + (lane & 15)*USTR + ((lane >> 4) & 1)*16;

#pragma unroll
        for (int tp = 0; tp < 8; tp++) {     // 16 f per iteration
            uint32_t A4[4];
#pragma unroll
            for (int h = 0; h < 2; h++) {
                const int f0 = fs + (2*tp + h)*8;
                const uint32_t kb0 = __float_as_uint(__ldg(kpt + (tg    <<12) + f0 + g));
                const uint32_t kb1 = __float_as_uint(__ldg(kpt + ((tg+4)<<12) + f0 + g));
                float s0, s1, s2, s3;
                mma_tf32_z(s0, s1, s2, s3, aq0, aq1, aq2, aq3, kb0, kb1);
                float e0, e1, e2, e3;
                EX2F(e0, s0); EX2F(e1, s1); EX2F(e2, s2); EX2F(e3, s3);
                CVT_BF16X2_F32(A4[2*h],     e0, e1);
                CVT_BF16X2_F32(A4[2*h + 1], e2, e3);
            }
            const uint32_t la0 = ldb + tp*16*USTR;
#pragma unroll
            for (int nn = 0; nn < 4; nn++) {
                uint32_t b0, b1, b2, b3;
                ldmatrix_x4_trans(b0, b1, b2, b3, la0 + nn*32);
                mma16816(acc[2*nn],     A4, b0, b1);
                mma16816(acc[2*nn + 1], A4, b2, b3);
            }
        }
    }

    // ---- direct epilogue: out = gamma*acc + x
    const float gm = *gamma;
#pragma unroll
    for (int m = 0; m < 8; m++) {
        const int co = m*8 + tg*2;
        const size_t i00 = (((size_t)(b*C + co)) << 14) + qa;
        const size_t i10 = i00 + (size_t)(1 << 14);
        out[i00]     = fmaf(gm, acc[m][0], __ldg(x + i00));
        out[i10]     = fmaf(gm, acc[m][1], __ldg(x + i10));
        out[i00 + 8] = fmaf(gm, acc[m][2], __ldg(x + i00 + 8));
        out[i10 + 8] = fmaf(gm, acc[m][3], __ldg(x + i10 + 8));
    }
}

extern "C" void kernel_launch(void* const* d_in, const int* in_sizes, int n_in,
                              void* d_out, int out_size) {
    const float* x     = (const float*)d_in[0];
    const float* Wq    = (const float*)d_in[1];
    const float* Wk    = (const float*)d_in[2];
    const float* Wv    = (const float*)d_in[3];
    const float* Wo    = (const float*)d_in[4];
    const float* gamma = (const float*)d_in[5];
    float* out = (float*)d_out;

    k_proj      <<< NB*HWD/128, 128 >>> (x, Wq, Wk, Wv);
    k_stats_mma <<< NB*512, 256 >>> ();
    k_uvt       <<< NB*F/128, 256 >>> (Wo);
    dim3 g4(HWD/TK, NB);
    k_attn_mma  <<< g4, 256 >>> (x, gamma, out);
}

// round 6
// speedup vs baseline: 3.4988x; 1.0771x over previous
#include <cuda_runtime.h>
#include <cuda_bf16.h>
#include <cuda_fp16.h>
#include <math.h>
#include <float.h>
#include <stdint.h>

// Shapes (fixed by the problem)
#define NB  4
#define C   64
#define HH  128
#define HWD (128*128)   // 16384 full-res positions per batch
#define F   4096        // 64x64 pooled positions per batch
#define CQ  8           // query/key channels
#define CV  32          // value channels
#define TK  128         // queries per attn block (MMA M)
#define SFC 128         // f per stage in attn
#define VSTR 80         // v smem row stride bytes (64 -> 80 pad, conflict-free ldmatrix)
#define LOG2E 1.4426950408889634f

// ---------------- scratch (device globals) ----------------
__device__ float g_q  [NB*CQ*HWD];         // [b][c][k]  tf32-rounded q
__device__ float g_kpt[NB*CQ*F];           // [b][c][f]  tf32-rounded kp * log2e
__device__ float g_v  [NB*F*CV];           // [b][f][c]  raw pooled v (fp32)
__device__ float g_z  [NB*F];              // Z[b][f] (atomic accum)
__device__ float g_zl [NB*F];              // log2(Z)
__device__ __half g_v16[NB*F*CV];          // [b][f][c]  fp16 v (V-MMA B operand)

// ---------------- PTX helpers (baseline PTX only) ----------------
__device__ __forceinline__ uint32_t smem_u32(const void* p) {
    uint32_t a;
    asm("{ .reg .u64 t; cvta.to.shared.u64 t, %1; cvt.u32.u64 %0, t; }" : "=r"(a) : "l"(p));
    return a;
}
// res = bf16x2 {lo=a, hi=b}
#define CVT_BF16X2_F32(res, a, b) \
    asm("cvt.rn.bf16x2.f32 %0, %1, %2;" : "=r"(res) : "f"(b), "f"(a))
// res = f16x2 {lo=a, hi=b}
#define CVT_F16X2_F32(res, a, b) \
    asm("cvt.rn.f16x2.f32 %0, %1, %2;" : "=r"(res) : "f"(b), "f"(a))
#define EX2F(d, s)   asm("ex2.approx.f32 %0, %1;" : "=f"(d) : "f"(s))
#define EX2H2(d, s)  asm("ex2.approx.f16x2 %0, %1;" : "=r"(d) : "r"(s))
#define LG2F(d, s)   asm("lg2.approx.f32 %0, %1;" : "=f"(d) : "f"(s))
#define TF32R(u, v)  asm("cvt.rna.tf32.f32 %0, %1;" : "=r"(u) : "f"(v))
#define CP_ASYNC16(dst, src) \
    asm volatile("cp.async.ca.shared.global [%0], [%1], 16;" :: "r"(dst), "l"(src))
#define CP_ASYNC4(dst, src) \
    asm volatile("cp.async.ca.shared.global [%0], [%1], 4;" :: "r"(dst), "l"(src))
#define CP_COMMIT asm volatile("cp.async.commit_group;" ::: "memory")
#define CP_WAIT0  asm volatile("cp.async.wait_group 0;" ::: "memory")

__device__ __forceinline__ void ldmatrix_x4_trans(uint32_t& r0, uint32_t& r1,
                                                  uint32_t& r2, uint32_t& r3,
                                                  uint32_t addr) {
    asm volatile("ldmatrix.sync.aligned.m8n8.x4.trans.shared.b16 {%0,%1,%2,%3}, [%4];"
        : "=r"(r0), "=r"(r1), "=r"(r2), "=r"(r3) : "r"(addr));
}
// bf16 m16n8k16 (stats Z rowsum), accumulate
__device__ __forceinline__ void mma16816bf(float* d, const uint32_t* a,
                                           uint32_t b0, uint32_t b1) {
    asm volatile(
      "mma.sync.aligned.m16n8k16.row.col.f32.bf16.bf16.f32 "
      "{%0,%1,%2,%3}, {%4,%5,%6,%7}, {%8,%9}, {%0,%1,%2,%3};"
      : "+f"(d[0]), "+f"(d[1]), "+f"(d[2]), "+f"(d[3])
      : "r"(a[0]), "r"(a[1]), "r"(a[2]), "r"(a[3]), "r"(b0), "r"(b1));
}
// fp16 m16n8k16 (V-MMA), fp32 acc, accumulate
__device__ __forceinline__ void mma16816h(float* d, const uint32_t* a,
                                          uint32_t b0, uint32_t b1) {
    asm volatile(
      "mma.sync.aligned.m16n8k16.row.col.f32.f16.f16.f32 "
      "{%0,%1,%2,%3}, {%4,%5,%6,%7}, {%8,%9}, {%0,%1,%2,%3};"
      : "+f"(d[0]), "+f"(d[1]), "+f"(d[2]), "+f"(d[3])
      : "r"(a[0]), "r"(a[1]), "r"(a[2]), "r"(a[3]), "r"(b0), "r"(b1));
}
// tf32 m16n8k8, C = 0 (fresh scores)
__device__ __forceinline__ void mma_tf32_z(float& d0, float& d1, float& d2, float& d3,
                                           uint32_t a0, uint32_t a1, uint32_t a2, uint32_t a3,
                                           uint32_t b0, uint32_t b1) {
    asm volatile(
      "mma.sync.aligned.m16n8k8.row.col.f32.tf32.tf32.f32 "
      "{%0,%1,%2,%3}, {%4,%5,%6,%7}, {%8,%9}, {%10,%11,%12,%13};"
      : "=f"(d0), "=f"(d1), "=f"(d2), "=f"(d3)
      : "r"(a0), "r"(a1), "r"(a2), "r"(a3), "r"(b0), "r"(b1),
        "f"(0.f), "f"(0.f), "f"(0.f), "f"(0.f));
}

// ---------------- K1: merged projections + 2x2 maxpool via shfl ----------------
__global__ __launch_bounds__(128) void k_proj(const float* __restrict__ x,
                                              const float* __restrict__ Wq,
                                              const float* __restrict__ Wk,
                                              const float* __restrict__ Wv) {
    __shared__ float wT[C][48];   // [c][0:8 q | 8:16 k | 16:48 v]
    for (int i = threadIdx.x; i < C*48; i += 128) {
        int c = i / 48, j = i - c*48;
        float v;
        if (j < 8)       v = Wq[j*C + c];
        else if (j < 16) v = Wk[(j-8)*C + c];
        else             v = Wv[(j-16)*C + c];
        wT[c][j] = v;
    }
    __syncthreads();

    const int t = threadIdx.x;
    const int p = blockIdx.x*128 + t;
    const int cell = p >> 2;
    const int b = cell >> 12;
    const int f = cell & 4095;
    const int ph = f >> 6, pw = f & 63;
    const int h = 2*ph + ((t >> 1) & 1);
    const int w = 2*pw + (t & 1);
    const int hw = h*HH + w;
    const float* xp = x + (size_t)b*C*HWD + hw;

    float acc[48];
#pragma unroll
    for (int j = 0; j < 48; j++) acc[j] = 0.f;

#pragma unroll 4
    for (int c = 0; c < C; c++) {
        const float xv = __ldg(xp + c*HWD);
        const float4* wr = reinterpret_cast<const float4*>(&wT[c][0]);
#pragma unroll
        for (int j4 = 0; j4 < 12; j4++) {
            float4 ww = wr[j4];
            acc[4*j4+0] = fmaf(ww.x, xv, acc[4*j4+0]);
            acc[4*j4+1] = fmaf(ww.y, xv, acc[4*j4+1]);
            acc[4*j4+2] = fmaf(ww.z, xv, acc[4*j4+2]);
            acc[4*j4+3] = fmaf(ww.w, xv, acc[4*j4+3]);
        }
    }

#pragma unroll
    for (int o = 0; o < CQ; o++) {
        uint32_t u; TF32R(u, acc[o]);
        g_q[((b*CQ+o)<<14) + hw] = __uint_as_float(u);
    }

#pragma unroll
    for (int j = 8; j < 48; j++) {
        float m = acc[j];
        m = fmaxf(m, __shfl_xor_sync(0xffffffffu, m, 1));
        m = fmaxf(m, __shfl_xor_sync(0xffffffffu, m, 2));
        acc[j] = m;
    }
    if ((t & 3) == 0) {
#pragma unroll
        for (int o = 0; o < CQ; o++) {
            uint32_t u; TF32R(u, acc[8+o] * LOG2E);
            g_kpt[((b*CQ+o)<<12) + f] = __uint_as_float(u);
        }
        float* vp = g_v + ((size_t)(b*F + f))*CV;
#pragma unroll
        for (int o = 0; o < CV; o++) vp[o] = acc[16+o];
        g_z[b*F + f] = 0.f;
    }
}

// ---------------- K2: partial Z via score-MMA + ones-MMA, atomic accumulate ----
__global__ __launch_bounds__(256) void k_stats_mma() {
    const int blk = blockIdx.x;
    const int b = blk >> 9;
    const int r = blk & 511;
    const int f0blk = (r >> 3) * 64;
    const int qsp = r & 7;
    const int tid = threadIdx.x;
    const int w = tid >> 5, lane = tid & 31;
    const int g = lane >> 2, tg = lane & 3;
    const int wf = w & 3, wq = w >> 2;
    const int fm = f0blk + wf*16;

    const float* kpt = g_kpt + ((size_t)(b*CQ) << 12);
    const uint32_t a0 = __float_as_uint(kpt[(tg    <<12) + fm + g    ]);
    const uint32_t a1 = __float_as_uint(kpt[(tg    <<12) + fm + g + 8]);
    const uint32_t a2 = __float_as_uint(kpt[((tg+4)<<12) + fm + g    ]);
    const uint32_t a3 = __float_as_uint(kpt[((tg+4)<<12) + fm + g + 8]);

    const float* qp = g_q + ((size_t)(b*CQ) << 14);
    const int q0 = qsp*2048 + wq*1024;
    const uint32_t ONES = 0x3F803F80u;

    float z[4] = {0.f, 0.f, 0.f, 0.f};

    for (int st = 0; st < 16; st++) {
        const int qs = q0 + st*64;
#pragma unroll
        for (int tp = 0; tp < 4; tp++) {
            uint32_t A4[4];
#pragma unroll
            for (int h = 0; h < 2; h++) {
                const int qc = qs + (2*tp + h)*8 + g;
                const uint32_t b0 = __float_as_uint(__ldg(qp + (tg    <<14) + qc));
                const uint32_t b1 = __float_as_uint(__ldg(qp + ((tg+4)<<14) + qc));
                float s0, s1, s2, s3;
                mma_tf32_z(s0, s1, s2, s3, a0, a1, a2, a3, b0, b1);
                float e0, e1, e2, e3;
                EX2F(e0, s0); EX2F(e1, s1); EX2F(e2, s2); EX2F(e3, s3);
                CVT_BF16X2_F32(A4[2*h],     e0, e1);
                CVT_BF16X2_F32(A4[2*h + 1], e2, e3);
            }
            mma16816bf(z, A4, ONES, ONES);
        }
    }

    __shared__ float zs[2][64];
    if (tg == 0) {
        zs[wq][wf*16 + g    ] = z[0];
        zs[wq][wf*16 + g + 8] = z[2];
    }
    __syncthreads();
    if (tid < 64)
        atomicAdd(&g_z[b*F + f0blk + tid], zs[0][tid] + zs[1][tid]);
}

// ---------------- K3: zl = log2(Z), v16 = fp16(v) ----------------
__global__ __launch_bounds__(256) void k_uvt() {
    const int fi = blockIdx.x*256 + threadIdx.x;   // over NB*F
    float zl; LG2F(zl, g_z[fi]);
    g_zl[fi] = zl;

    const float4* vp = reinterpret_cast<const float4*>(g_v + (size_t)fi*CV);
    uint32_t packed[16];
#pragma unroll
    for (int i = 0; i < 8; i++) {
        float4 t4 = vp[i];
        CVT_F16X2_F32(packed[2*i],     t4.x, t4.y);
        CVT_F16X2_F32(packed[2*i + 1], t4.z, t4.w);
    }
    uint4* up = reinterpret_cast<uint4*>(
        reinterpret_cast<char*>(g_v16) + ((size_t)fi*CV)*2);
    const uint4* ps = reinterpret_cast<const uint4*>(packed);
#pragma unroll
    for (int i = 0; i < 4; i++) up[i] = ps[i];
}

// ---------------- K4: tensorized attention (fp16 E', N=32) + Wo epilogue ------
// E'[f,q] = 2^(s[f,q] - log2 Z[f]) in fp16 (normalized weight, <= 1)
// acc[128q,32c] = E' x fp16(v);  out = gamma * (Wo @ acc) + x
__global__ __launch_bounds__(256) void k_attn_mma(const float* __restrict__ x,
                                                  const float* __restrict__ Wo,
                                                  const float* __restrict__ gamma,
                                                  float* __restrict__ out) {
    // union pool: staging (2 x 10240 v + 2 x 512 zl = 21504) vs epilogue (8192 wo + 16896 out_s)
    __shared__ __align__(16) char pool[25088];
    const uint32_t pb = smem_u32(pool);
    const uint32_t VB0 = pb, VB1 = pb + 10240;
    const uint32_t ZB0 = pb + 20480, ZB1 = pb + 20992;

    const int tid = threadIdx.x;
    const int w = tid >> 5, lane = tid & 31;
    const int g = lane >> 2, tg = lane & 3;
    const int b = blockIdx.y;
    const int kbase = blockIdx.x * TK;

    // persistent A (q) tf32 fragments
    const int la = w*16 + g;
    const int qa = kbase + la, qb = qa + 8;
    const float* qp = g_q + ((size_t)(b*CQ) << 14);
    const uint32_t aq0 = __float_as_uint(qp[(tg    <<14) + qa]);
    const uint32_t aq1 = __float_as_uint(qp[(tg    <<14) + qb]);
    const uint32_t aq2 = __float_as_uint(qp[((tg+4)<<14) + qa]);
    const uint32_t aq3 = __float_as_uint(qp[((tg+4)<<14) + qb]);

    const float* kpt = g_kpt + ((size_t)(b*CQ) << 12);
    const char* vbat = reinterpret_cast<const char*>(g_v16) + (((size_t)b*F*CV) << 1);
    const char* zbat = reinterpret_cast<const char*>(g_zl) + (((size_t)b*F) << 2);

    float acc[4][4];
#pragma unroll
    for (int i = 0; i < 4; i++)
#pragma unroll
        for (int j = 0; j < 4; j++) acc[i][j] = 0.f;

    // prologue: stage 0 (v rows 64B -> 80B stride; zl 512B)
#pragma unroll
    for (int k = 0; k < 2; k++) {
        int id = tid + k*256, row = id >> 2, seg = id & 3;
        CP_ASYNC16(VB0 + row*VSTR + seg*16, vbat + ((size_t)row << 6) + seg*16);
    }
    if (tid < SFC) CP_ASYNC4(ZB0 + tid*4, zbat + tid*4);
    CP_COMMIT;

    const int NST = F / SFC;   // 32
    for (int st = 0; st < NST; st++) {
        CP_WAIT0;
        __syncthreads();
        if (st + 1 < NST) {
            const int nb = (st + 1) & 1;
            const uint32_t vdst = nb ? VB1 : VB0;
            const uint32_t zdst = nb ? ZB1 : ZB0;
            const char* vsrc = vbat + (((size_t)(st+1)*SFC*CV) << 1);
            const char* zsrc = zbat + (((size_t)(st+1)*SFC) << 2);
#pragma unroll
            for (int k = 0; k < 2; k++) {
                int id = tid + k*256, row = id >> 2, seg = id & 3;
                CP_ASYNC16(vdst + row*VSTR + seg*16, vsrc + ((size_t)row << 6) + seg*16);
            }
            if (tid < SFC) CP_ASYNC4(zdst + tid*4, zsrc + tid*4);
            CP_COMMIT;
        }
        const int fs = st * SFC;
        const int cb = st & 1;
        const uint32_t ldb = (cb ? VB1 : VB0) + (lane & 15)*VSTR + ((lane >> 4) & 1)*16;
        const float2* zlp = reinterpret_cast<const float2*>(pool + (cb ? 20992 : 20480));

#pragma unroll
        for (int tp = 0; tp < 8; tp++) {     // 16 f per iteration
            uint32_t A4[4];
#pragma unroll
            for (int h = 0; h < 2; h++) {
                const int fo = (2*tp + h)*8;         // f offset within stage
                const int f0 = fs + fo;
                const uint32_t kb0 = __float_as_uint(__ldg(kpt + (tg    <<12) + f0 + g));
                const uint32_t kb1 = __float_as_uint(__ldg(kpt + ((tg+4)<<12) + f0 + g));
                float s0, s1, s2, s3;
                mma_tf32_z(s0, s1, s2, s3, aq0, aq1, aq2, aq3, kb0, kb1);
                const float2 zl2 = zlp[(fo >> 1) + tg];   // zl[f0+2tg], zl[f0+2tg+1]
                uint32_t p0, p1;
                CVT_F16X2_F32(p0, s0 - zl2.x, s1 - zl2.y);   // row qa
                CVT_F16X2_F32(p1, s2 - zl2.x, s3 - zl2.y);   // row qb
                EX2H2(A4[2*h],     p0);
                EX2H2(A4[2*h + 1], p1);
            }
            const uint32_t la0 = ldb + tp*16*VSTR;
            uint32_t b0, b1, b2, b3, b4, b5, b6, b7;
            ldmatrix_x4_trans(b0, b1, b2, b3, la0);        // channels 0..15
            ldmatrix_x4_trans(b4, b5, b6, b7, la0 + 32);   // channels 16..31
            mma16816h(acc[0], A4, b0, b1);
            mma16816h(acc[1], A4, b2, b3);
            mma16816h(acc[2], A4, b4, b5);
            mma16816h(acc[3], A4, b6, b7);
        }
    }

    // ---- epilogue: acc -> out_s, y = Wo @ acc32, out = gamma*y + x
    __syncthreads();   // all staging reads done; reuse pool
    float* wo_s  = reinterpret_cast<float*>(pool);            // 8KB
    float (*out_s)[33] = reinterpret_cast<float(*)[33]>(pool + 8192);  // 16.9KB
    for (int i = tid; i < C*CV; i += 256) wo_s[i] = Wo[i];
#pragma unroll
    for (int nc = 0; nc < 4; nc++) {
        out_s[la    ][nc*8 + tg*2    ] = acc[nc][0];
        out_s[la    ][nc*8 + tg*2 + 1] = acc[nc][1];
        out_s[la + 8][nc*8 + tg*2    ] = acc[nc][2];
        out_s[la + 8][nc*8 + tg*2 + 1] = acc[nc][3];
    }
    __syncthreads();

    const int klane = tid & 127;
    float col[CV];
#pragma unroll
    for (int c = 0; c < CV; c++) col[c] = out_s[klane][c];
    const float gm = *gamma;
    const int co0 = (tid >> 7) * 32;
#pragma unroll 4
    for (int co = 0; co < 32; co++) {
        float y = 0.f;
#pragma unroll
        for (int c = 0; c < CV; c++) y = fmaf(wo_s[(co0+co)*CV + c], col[c], y);
        size_t oidx = ((size_t)(b*C + co0 + co) << 14) + kbase + klane;
        out[oidx] = fmaf(gm, y, __ldg(x + oidx));
    }
}

extern "C" void kernel_launch(void* const* d_in, const int* in_sizes, int n_in,
                              void* d_out, int out_size) {
    const float* x     = (const float*)d_in[0];
    const float* Wq    = (const float*)d_in[1];
    const float* Wk    = (const float*)d_in[2];
    const float* Wv    = (const float*)d_in[3];
    const float* Wo    = (const float*)d_in[4];
    const float* gamma = (const float*)d_in[5];
    float* out = (float*)d_out;

    k_proj      <<< NB*HWD/128, 128 >>> (x, Wq, Wk, Wv);
    k_stats_mma <<< NB*512, 256 >>> ();
    k_uvt       <<< NB*F/256, 256 >>> ();
    dim3 g4(HWD/TK, NB);
    k_attn_mma  <<< g4, 256 >>> (x, Wo, gamma, out);
}

// round 7
// speedup vs baseline: 5.1725x; 1.4784x over previous
#include <cuda_runtime.h>
#include <cuda_bf16.h>
#include <cuda_fp16.h>
#include <math.h>
#include <float.h>
#include <stdint.h>

// Shapes (fixed by the problem)
#define NB  4
#define C   64
#define HH  128
#define HWD (128*128)   // 16384 full-res positions per batch
#define F   4096        // 64x64 pooled positions per batch
#define CQ  8           // query/key channels
#define CV  32          // value channels
#define TK  128         // queries per attn block (MMA M)
#define SFC 128         // f per stage in attn
#define VSTR 80         // v smem row stride bytes (64 -> 80 pad, conflict-free ldmatrix)
#define LOG2E 1.4426950408889634f

// ---------------- scratch (device globals) ----------------
// fragment-ordered: [b][idx/8][c*8 + idx%8]  (one MMA B/A fragment word per lane)
__device__ float g_qf [NB*(HWD/8)*64];     // q (tf32-rounded)
__device__ float g_kpf[NB*(F/8)*64];       // kp * log2e (tf32-rounded)
__device__ float g_kpt[NB*CQ*F];           // [b][c][f] kp*log2e (stats persistent A)
__device__ float g_v  [NB*F*CV];           // [b][f][c] raw pooled v (fp32)
__device__ float g_z  [NB*F];              // Z[b][f] (atomic accum)
__device__ float g_zl [NB*F];              // log2(Z)
__device__ __half g_v16[NB*F*CV];          // [b][f][c] fp16 v (V-MMA B operand)

// ---------------- PTX helpers (baseline PTX only) ----------------
__device__ __forceinline__ uint32_t smem_u32(const void* p) {
    uint32_t a;
    asm("{ .reg .u64 t; cvta.to.shared.u64 t, %1; cvt.u32.u64 %0, t; }" : "=r"(a) : "l"(p));
    return a;
}
#define CVT_BF16X2_F32(res, a, b) \
    asm("cvt.rn.bf16x2.f32 %0, %1, %2;" : "=r"(res) : "f"(b), "f"(a))
#define CVT_F16X2_F32(res, a, b) \
    asm("cvt.rn.f16x2.f32 %0, %1, %2;" : "=r"(res) : "f"(b), "f"(a))
#define EX2F(d, s)   asm("ex2.approx.f32 %0, %1;" : "=f"(d) : "f"(s))
#define EX2H2(d, s)  asm("ex2.approx.f16x2 %0, %1;" : "=r"(d) : "r"(s))
#define LG2F(d, s)   asm("lg2.approx.f32 %0, %1;" : "=f"(d) : "f"(s))
#define TF32R(u, v)  asm("cvt.rna.tf32.f32 %0, %1;" : "=r"(u) : "f"(v))
#define LDS32(d, a) \
    asm volatile("ld.shared.b32 %0, [%1];" : "=r"(d) : "r"(a))
#define CP_ASYNC16(dst, src) \
    asm volatile("cp.async.ca.shared.global [%0], [%1], 16;" :: "r"(dst), "l"(src))
#define CP_COMMIT asm volatile("cp.async.commit_group;" ::: "memory")
#define CP_WAIT0  asm volatile("cp.async.wait_group 0;" ::: "memory")

__device__ __forceinline__ void ldmatrix_x4_trans(uint32_t& r0, uint32_t& r1,
                                                  uint32_t& r2, uint32_t& r3,
                                                  uint32_t addr) {
    asm volatile("ldmatrix.sync.aligned.m8n8.x4.trans.shared.b16 {%0,%1,%2,%3}, [%4];"
        : "=r"(r0), "=r"(r1), "=r"(r2), "=r"(r3) : "r"(addr));
}
__device__ __forceinline__ void mma16816bf(float* d, const uint32_t* a,
                                           uint32_t b0, uint32_t b1) {
    asm volatile(
      "mma.sync.aligned.m16n8k16.row.col.f32.bf16.bf16.f32 "
      "{%0,%1,%2,%3}, {%4,%5,%6,%7}, {%8,%9}, {%0,%1,%2,%3};"
      : "+f"(d[0]), "+f"(d[1]), "+f"(d[2]), "+f"(d[3])
      : "r"(a[0]), "r"(a[1]), "r"(a[2]), "r"(a[3]), "r"(b0), "r"(b1));
}
__device__ __forceinline__ void mma16816h(float* d, const uint32_t* a,
                                          uint32_t b0, uint32_t b1) {
    asm volatile(
      "mma.sync.aligned.m16n8k16.row.col.f32.f16.f16.f32 "
      "{%0,%1,%2,%3}, {%4,%5,%6,%7}, {%8,%9}, {%0,%1,%2,%3};"
      : "+f"(d[0]), "+f"(d[1]), "+f"(d[2]), "+f"(d[3])
      : "r"(a[0]), "r"(a[1]), "r"(a[2]), "r"(a[3]), "r"(b0), "r"(b1));
}
__device__ __forceinline__ void mma_tf32_z(float& d0, float& d1, float& d2, float& d3,
                                           uint32_t a0, uint32_t a1, uint32_t a2, uint32_t a3,
                                           uint32_t b0, uint32_t b1) {
    asm volatile(
      "mma.sync.aligned.m16n8k8.row.col.f32.tf32.tf32.f32 "
      "{%0,%1,%2,%3}, {%4,%5,%6,%7}, {%8,%9}, {%10,%11,%12,%13};"
      : "=f"(d0), "=f"(d1), "=f"(d2), "=f"(d3)
      : "r"(a0), "r"(a1), "r"(a2), "r"(a3), "r"(b0), "r"(b1),
        "f"(0.f), "f"(0.f), "f"(0.f), "f"(0.f));
}

// ---------------- K1: merged projections + 2x2 maxpool via shfl ----------------
__global__ __launch_bounds__(128) void k_proj(const float* __restrict__ x,
                                              const float* __restrict__ Wq,
                                              const float* __restrict__ Wk,
                                              const float* __restrict__ Wv) {
    __shared__ float wT[C][48];   // [c][0:8 q | 8:16 k | 16:48 v]
    for (int i = threadIdx.x; i < C*48; i += 128) {
        int c = i / 48, j = i - c*48;
        float v;
        if (j < 8)       v = Wq[j*C + c];
        else if (j < 16) v = Wk[(j-8)*C + c];
        else             v = Wv[(j-16)*C + c];
        wT[c][j] = v;
    }
    __syncthreads();

    const int t = threadIdx.x;
    const int p = blockIdx.x*128 + t;
    const int cell = p >> 2;
    const int b = cell >> 12;
    const int f = cell & 4095;
    const int ph = f >> 6, pw = f & 63;
    const int h = 2*ph + ((t >> 1) & 1);
    const int w = 2*pw + (t & 1);
    const int hw = h*HH + w;
    const float* xp = x + (size_t)b*C*HWD + hw;

    float acc[48];
#pragma unroll
    for (int j = 0; j < 48; j++) acc[j] = 0.f;

#pragma unroll 4
    for (int c = 0; c < C; c++) {
        const float xv = __ldg(xp + c*HWD);
        const float4* wr = reinterpret_cast<const float4*>(&wT[c][0]);
#pragma unroll
        for (int j4 = 0; j4 < 12; j4++) {
            float4 ww = wr[j4];
            acc[4*j4+0] = fmaf(ww.x, xv, acc[4*j4+0]);
            acc[4*j4+1] = fmaf(ww.y, xv, acc[4*j4+1]);
            acc[4*j4+2] = fmaf(ww.z, xv, acc[4*j4+2]);
            acc[4*j4+3] = fmaf(ww.w, xv, acc[4*j4+3]);
        }
    }

    // q -> fragment-ordered g_qf
    {
        float* qg = g_qf + ((size_t)(b*(HWD/8) + (hw >> 3)) << 6) + (hw & 7);
#pragma unroll
        for (int o = 0; o < CQ; o++) {
            uint32_t u; TF32R(u, acc[o]);
            qg[o*8] = __uint_as_float(u);
        }
    }

    // 2x2 max-pool for k and v via shuffles
#pragma unroll
    for (int j = 8; j < 48; j++) {
        float m = acc[j];
        m = fmaxf(m, __shfl_xor_sync(0xffffffffu, m, 1));
        m = fmaxf(m, __shfl_xor_sync(0xffffffffu, m, 2));
        acc[j] = m;
    }
    if ((t & 3) == 0) {
        float* kg = g_kpf + ((size_t)(b*(F/8) + (f >> 3)) << 6) + (f & 7);
#pragma unroll
        for (int o = 0; o < CQ; o++) {
            uint32_t u; TF32R(u, acc[8+o] * LOG2E);
            float kv = __uint_as_float(u);
            kg[o*8] = kv;
            g_kpt[((b*CQ+o)<<12) + f] = kv;
        }
        float* vp = g_v + ((size_t)(b*F + f))*CV;
#pragma unroll
        for (int o = 0; o < CV; o++) vp[o] = acc[16+o];
        g_z[b*F + f] = 0.f;
    }
}

// ---------------- K2: partial Z via score-MMA + ones-MMA, atomic accumulate ----
__global__ __launch_bounds__(256) void k_stats_mma() {
    const int blk = blockIdx.x;
    const int b = blk >> 9;
    const int r = blk & 511;
    const int f0blk = (r >> 3) * 64;
    const int qsp = r & 7;
    const int tid = threadIdx.x;
    const int w = tid >> 5, lane = tid & 31;
    const int g = lane >> 2, tg = lane & 3;
    const int wf = w & 3, wq = w >> 2;
    const int fm = f0blk + wf*16;

    const float* kpt = g_kpt + ((size_t)(b*CQ) << 12);
    const uint32_t a0 = __float_as_uint(kpt[(tg    <<12) + fm + g    ]);
    const uint32_t a1 = __float_as_uint(kpt[(tg    <<12) + fm + g + 8]);
    const uint32_t a2 = __float_as_uint(kpt[((tg+4)<<12) + fm + g    ]);
    const uint32_t a3 = __float_as_uint(kpt[((tg+4)<<12) + fm + g + 8]);

    // coalesced fragment loads from g_qf
    const float* qf = g_qf + ((size_t)(b*(HWD/8)) << 6);
    const int frag = tg*8 + g;           // lane word
    const int qg0 = qsp*256 + wq*128;    // base q-group
    const uint32_t ONES = 0x3F803F80u;

    float z[4] = {0.f, 0.f, 0.f, 0.f};

    for (int st = 0; st < 16; st++) {
        const int gbase = qg0 + st*8;
#pragma unroll
        for (int tp = 0; tp < 4; tp++) {
            uint32_t A4[4];
#pragma unroll
            for (int h = 0; h < 2; h++) {
                const float* fp = qf + (((size_t)(gbase + 2*tp + h)) << 6) + frag;
                const uint32_t b0 = __float_as_uint(__ldg(fp));
                const uint32_t b1 = __float_as_uint(__ldg(fp + 32));
                float s0, s1, s2, s3;
                mma_tf32_z(s0, s1, s2, s3, a0, a1, a2, a3, b0, b1);
                float e0, e1, e2, e3;
                EX2F(e0, s0); EX2F(e1, s1); EX2F(e2, s2); EX2F(e3, s3);
                CVT_BF16X2_F32(A4[2*h],     e0, e1);
                CVT_BF16X2_F32(A4[2*h + 1], e2, e3);
            }
            mma16816bf(z, A4, ONES, ONES);
        }
    }

    __shared__ float zs[2][64];
    if (tg == 0) {
        zs[wq][wf*16 + g    ] = z[0];
        zs[wq][wf*16 + g + 8] = z[2];
    }
    __syncthreads();
    if (tid < 64)
        atomicAdd(&g_z[b*F + f0blk + tid], zs[0][tid] + zs[1][tid]);
}

// ---------------- K3: zl = log2(Z), v16 = fp16(v) ----------------
__global__ __launch_bounds__(256) void k_uvt() {
    const int fi = blockIdx.x*256 + threadIdx.x;   // over NB*F
    float zl; LG2F(zl, g_z[fi]);
    g_zl[fi] = zl;

    const float4* vp = reinterpret_cast<const float4*>(g_v + (size_t)fi*CV);
    uint32_t packed[16];
#pragma unroll
    for (int i = 0; i < 8; i++) {
        float4 t4 = vp[i];
        CVT_F16X2_F32(packed[2*i],     t4.x, t4.y);
        CVT_F16X2_F32(packed[2*i + 1], t4.z, t4.w);
    }
    uint4* up = reinterpret_cast<uint4*>(
        reinterpret_cast<char*>(g_v16) + ((size_t)fi*CV)*2);
    const uint4* ps = reinterpret_cast<const uint4*>(packed);
#pragma unroll
    for (int i = 0; i < 4; i++) up[i] = ps[i];
}

// ---------------- K4: tensorized attention, LDS fragments, 4 blocks/SM --------
// E'[f,q] = 2^(s - log2 Z[f]) fp16; acc = E' x fp16(v); out = gamma*(Wo@acc)+x
// Stage buffers (double): v 10240B | kpf 4096B | zl 512B  = 14848B each
#define STG 14848
#define KPOFF 10240
#define ZOFF  14336
__global__ __launch_bounds__(256, 4) void k_attn_mma(const float* __restrict__ x,
                                                     const float* __restrict__ Wo,
                                                     const float* __restrict__ gamma,
                                                     float* __restrict__ out) {
    __shared__ __align__(16) char pool[2*STG];   // 29696B; epilogue reuses 25088B
    const uint32_t pb = smem_u32(pool);

    const int tid = threadIdx.x;
    const int w = tid >> 5, lane = tid & 31;
    const int g = lane >> 2, tg = lane & 3;
    const int b = blockIdx.y;
    const int kbase = blockIdx.x * TK;
    const int frag = (tg*8 + g)*4;       // lane byte offset within fragment block

    // persistent A (q) tf32 fragments from g_qf
    const int la = w*16 + g;
    const int qa = kbase + la, qb = qa + 8;
    const float* qf = g_qf + ((size_t)(b*(HWD/8)) << 6);
    const uint32_t aq0 = __float_as_uint(qf[((qa >> 3) << 6) + tg*8     + (qa & 7)]);
    const uint32_t aq1 = __float_as_uint(qf[((qb >> 3) << 6) + tg*8     + (qb & 7)]);
    const uint32_t aq2 = __float_as_uint(qf[((qa >> 3) << 6) + (tg+4)*8 + (qa & 7)]);
    const uint32_t aq3 = __float_as_uint(qf[((qb >> 3) << 6) + (tg+4)*8 + (qb & 7)]);

    const char* kpbat = reinterpret_cast<const char*>(g_kpf) + (((size_t)b*(F/8)) << 8);
    const char* vbat  = reinterpret_cast<const char*>(g_v16) + (((size_t)b*F*CV) << 1);
    const char* zbat  = reinterpret_cast<const char*>(g_zl)  + (((size_t)b*F) << 2);

    float acc[4][4];
#pragma unroll
    for (int i = 0; i < 4; i++)
#pragma unroll
        for (int j = 0; j < 4; j++) acc[i][j] = 0.f;

    // prologue: stage 0
    {
#pragma unroll
        for (int k = 0; k < 2; k++) {
            int id = tid + k*256, row = id >> 2, seg = id & 3;
            CP_ASYNC16(pb + row*VSTR + seg*16, vbat + ((size_t)row << 6) + seg*16);
        }
        CP_ASYNC16(pb + KPOFF + tid*16, kpbat + tid*16);
        if (tid < 32) CP_ASYNC16(pb + ZOFF + tid*16, zbat + tid*16);
        CP_COMMIT;
    }

    const int NST = F / SFC;   // 32
    for (int st = 0; st < NST; st++) {
        CP_WAIT0;
        __syncthreads();
        if (st + 1 < NST) {
            const uint32_t sb = pb + ((st+1) & 1)*STG;
            const char* vsrc = vbat + (((size_t)(st+1)*SFC*CV) << 1);
            const char* ksrc = kpbat + (((size_t)(st+1)*(SFC/8)) << 8);
            const char* zsrc = zbat + (((size_t)(st+1)*SFC) << 2);
#pragma unroll
            for (int k = 0; k < 2; k++) {
                int id = tid + k*256, row = id >> 2, seg = id & 3;
                CP_ASYNC16(sb + row*VSTR + seg*16, vsrc + ((size_t)row << 6) + seg*16);
            }
            CP_ASYNC16(sb + KPOFF + tid*16, ksrc + tid*16);
            if (tid < 32) CP_ASYNC16(sb + ZOFF + tid*16, zsrc + tid*16);
            CP_COMMIT;
        }
        const uint32_t cb = pb + (st & 1)*STG;
        const uint32_t ldb = cb + (lane & 15)*VSTR + ((lane >> 4) & 1)*16;
        const uint32_t kpb = cb + KPOFF + frag;
        const float2* zlp = reinterpret_cast<const float2*>(
            pool + (st & 1)*STG + ZOFF);

#pragma unroll
        for (int tp = 0; tp < 8; tp++) {     // 16 f per iteration
            uint32_t A4[4];
#pragma unroll
            for (int h = 0; h < 2; h++) {
                const int gi = 2*tp + h;     // 8-f group within stage
                uint32_t kb0, kb1;
                LDS32(kb0, kpb + gi*256);
                LDS32(kb1, kpb + gi*256 + 128);
                float s0, s1, s2, s3;
                mma_tf32_z(s0, s1, s2, s3, aq0, aq1, aq2, aq3, kb0, kb1);
                const float2 zl2 = zlp[gi*4 + tg];
                uint32_t p0, p1;
                CVT_F16X2_F32(p0, s0 - zl2.x, s1 - zl2.y);
                CVT_F16X2_F32(p1, s2 - zl2.x, s3 - zl2.y);
                EX2H2(A4[2*h],     p0);
                EX2H2(A4[2*h + 1], p1);
            }
            const uint32_t la0 = ldb + tp*16*VSTR;
            uint32_t b0, b1, b2, b3, b4, b5, b6, b7;
            ldmatrix_x4_trans(b0, b1, b2, b3, la0);        // channels 0..15
            ldmatrix_x4_trans(b4, b5, b6, b7, la0 + 32);   // channels 16..31
            mma16816h(acc[0], A4, b0, b1);
            mma16816h(acc[1], A4, b2, b3);
            mma16816h(acc[2], A4, b4, b5);
            mma16816h(acc[3], A4, b6, b7);
        }
    }

    // ---- epilogue: acc -> out_s, y = Wo @ acc32, out = gamma*y + x
    __syncthreads();
    float* wo_s  = reinterpret_cast<float*>(pool);                      // 8KB
    float (*out_s)[33] = reinterpret_cast<float(*)[33]>(pool + 8192);   // 16.9KB
    for (int i = tid; i < C*CV; i += 256) wo_s[i] = Wo[i];
#pragma unroll
    for (int nc = 0; nc < 4; nc++) {
        out_s[la    ][nc*8 + tg*2    ] = acc[nc][0];
        out_s[la    ][nc*8 + tg*2 + 1] = acc[nc][1];
        out_s[la + 8][nc*8 + tg*2    ] = acc[nc][2];
        out_s[la + 8][nc*8 + tg*2 + 1] = acc[nc][3];
    }
    __syncthreads();

    const int klane = tid & 127;
    float col[CV];
#pragma unroll
    for (int c = 0; c < CV; c++) col[c] = out_s[klane][c];
    const float gm = *gamma;
    const int co0 = (tid >> 7) * 32;
#pragma unroll 4
    for (int co = 0; co < 32; co++) {
        float y = 0.f;
#pragma unroll
        for (int c = 0; c < CV; c++) y = fmaf(wo_s[(co0+co)*CV + c], col[c], y);
        size_t oidx = ((size_t)(b*C + co0 + co) << 14) + kbase + klane;
        out[oidx] = fmaf(gm, y, __ldg(x + oidx));
    }
}

extern "C" void kernel_launch(void* const* d_in, const int* in_sizes, int n_in,
                              void* d_out, int out_size) {
    const float* x     = (const float*)d_in[0];
    const float* Wq    = (const float*)d_in[1];
    const float* Wk    = (const float*)d_in[2];
    const float* Wv    = (const float*)d_in[3];
    const float* Wo    = (const float*)d_in[4];
    const float* gamma = (const float*)d_in[5];
    float* out = (float*)d_out;

    k_proj      <<< NB*HWD/128, 128 >>> (x, Wq, Wk, Wv);
    k_stats_mma <<< NB*512, 256 >>> ();
    k_uvt       <<< NB*F/256, 256 >>> ();
    dim3 g4(HWD/TK, NB);
    k_attn_mma  <<< g4, 256 >>> (x, Wo, gamma, out);
}